// round 15
// baseline (speedup 1.0000x reference)
#include <cuda_runtime.h>
#include <cuda_bf16.h>
#include <math.h>
#include <stdint.h>

// Problem constants
#define GG 32
#define NA 64
#define HH 300
#define AF 133
#define BF 147
#define AR (GG*NA)     // 2048
#define BR (GG*NA*NA)  // 131072
#define KP 320         // padded K for bond-step planes
#define KPI 160        // padded K for input_bond GEMM (BF=147 -> 160)

// Scratch (zero-initialized device globals; allocation-free)
__device__ float g_input_atom[AR*HH];
__device__ float g_msg_atom[AR*HH];
__device__ float g_agg[AR*HH];
__device__ float g_maW[AR*HH];
__device__ float g_input_bond[BR*HH];   // 157 MB fp32 (zero rows stay zero-init)
__device__ float g_mbB[BR*HH];          // fallback mb_final
__device__ float g_Cc[(size_t)BR*HH];   // compacted C = prev@W (step 0)
__device__ float g_sm[BR];
__device__ int   g_cnt;
__device__ int   g_rows[BR];
__device__ int   g_slot[BR];
// bf16 hi/lo planes (pads + zero rows never written -> stay zero)
__device__ __nv_bfloat16 g_P0h[(size_t)BR*KP];
__device__ __nv_bfloat16 g_P0l[(size_t)BR*KP];
__device__ __nv_bfloat16 g_P1h[(size_t)BR*KP];
__device__ __nv_bfloat16 g_P1l[(size_t)BR*KP];
__device__ __nv_bfloat16 g_Wt0h[KP*KP];
__device__ __nv_bfloat16 g_Wt0l[KP*KP];
__device__ __nv_bfloat16 g_Wt1h[KP*KP];
__device__ __nv_bfloat16 g_Wt1l[KP*KP];
__device__ __nv_bfloat16 g_WtIh[HH*KPI];
__device__ __nv_bfloat16 g_WtIl[HH*KPI];

// ---------------------------------------------------------------------------
// f32x2 helpers
// ---------------------------------------------------------------------------
__device__ __forceinline__ unsigned long long pack2(float x, float y) {
    unsigned long long r;
    asm("mov.b64 %0, {%1, %2};" : "=l"(r)
        : "r"(__float_as_uint(x)), "r"(__float_as_uint(y)));
    return r;
}
__device__ __forceinline__ void ffma2(unsigned long long& d, unsigned long long a,
                                      unsigned long long b) {
    asm("fma.rn.f32x2 %0, %1, %2, %3;" : "=l"(d) : "l"(a), "l"(b), "l"(d));
}
__device__ __forceinline__ float2 unpack2(unsigned long long v) {
    unsigned lo, hi;
    asm("mov.b64 {%0, %1}, %2;" : "=r"(lo), "=r"(hi) : "l"(v));
    return make_float2(__uint_as_float(lo), __uint_as_float(hi));
}

#define MMA_BF16(c, a, b0, b1) \
    asm volatile("mma.sync.aligned.m16n8k16.row.col.f32.bf16.bf16.f32 " \
                 "{%0,%1,%2,%3}, {%4,%5,%6,%7}, {%8,%9}, {%0,%1,%2,%3};" \
                 : "+f"((c)[0]), "+f"((c)[1]), "+f"((c)[2]), "+f"((c)[3]) \
                 : "r"((a)[0]), "r"((a)[1]), "r"((a)[2]), "r"((a)[3]), \
                   "r"(b0), "r"(b1))

#define LDSM_X4(R, A) \
    asm volatile("ldmatrix.sync.aligned.m8n8.x4.shared.b16 {%0,%1,%2,%3}, [%4];" \
                 : "=r"((R)[0]), "=r"((R)[1]), "=r"((R)[2]), "=r"((R)[3]) : "r"(A))

__device__ __forceinline__ uint32_t lds_addr(const void* p) {
    return (uint32_t)__cvta_generic_to_shared(p);
}

__device__ __forceinline__ void split_bf16(float v, __nv_bfloat16& h, __nv_bfloat16& l) {
    h = __float2bfloat16(v);
    l = __float2bfloat16(v - __bfloat162float(h));
}

// ---------------------------------------------------------------------------
// Sparse row compaction (adj is binary; ~30% density) + inverse slot map
// ---------------------------------------------------------------------------
__global__ void k_reset() { if (threadIdx.x == 0) g_cnt = 0; }

__global__ void k_compact(const float* __restrict__ adj) {
    int i = blockIdx.x * 256 + threadIdx.x;
    if (i < BR) {
        if (adj[i] != 0.f) {
            int idx = atomicAdd(&g_cnt, 1);
            g_rows[idx] = i;
            g_slot[i] = idx;
        } else {
            g_slot[i] = -1;
        }
    }
}

// ---------------------------------------------------------------------------
// W transpose + split (bond-step weights, KP layout)
// ---------------------------------------------------------------------------
__global__ void k_convW(const float* __restrict__ W,
                        __nv_bfloat16* __restrict__ hi, __nv_bfloat16* __restrict__ lo) {
    int n = blockIdx.x;
    int k = threadIdx.x;
    if (k < HH) {
        float v = W[(size_t)k * HH + n];
        __nv_bfloat16 h, l;
        split_bf16(v, h, l);
        hi[(size_t)n * KP + k] = h;
        lo[(size_t)n * KP + k] = l;
    }
}

// W_i_bond transpose + split (KPI layout, k in [BF,KPI) stays zero-init)
__global__ void k_convWi(const float* __restrict__ W,
                         __nv_bfloat16* __restrict__ hi, __nv_bfloat16* __restrict__ lo) {
    int n = blockIdx.x;          // 0..299
    int k = threadIdx.x;         // 0..159
    if (k < BF) {
        float v = W[(size_t)k * HH + n];
        __nv_bfloat16 h, l;
        split_bf16(v, h, l);
        hi[(size_t)n * KPI + k] = h;
        lo[(size_t)n * KPI + k] = l;
    }
}

// ---------------------------------------------------------------------------
// input_bond via mma.sync: compacted rows only.
// ---------------------------------------------------------------------------
__global__ __launch_bounds__(256)
void k_inbond_mma(const float* __restrict__ A,
                  const __nv_bfloat16* __restrict__ pWh, const __nv_bfloat16* __restrict__ pWl,
                  float* __restrict__ Co,
                  __nv_bfloat16* __restrict__ pH, __nv_bfloat16* __restrict__ pL) {
    extern __shared__ __align__(16) char smraw[];
    __nv_bfloat16 (*sAh)[40] = (__nv_bfloat16(*)[40])(smraw + 0);
    __nv_bfloat16 (*sAl)[40] = (__nv_bfloat16(*)[40])(smraw + 10240);
    __nv_bfloat16 (*sBh)[40] = (__nv_bfloat16(*)[40])(smraw + 20480);
    __nv_bfloat16 (*sBl)[40] = (__nv_bfloat16(*)[40])(smraw + 25600);

    const int cnt = g_cnt;
    const int row0 = blockIdx.y * 128;
    if (row0 >= cnt) return;
    const int col0 = blockIdx.x * 64;
    const int tid = threadIdx.x;
    const int w   = tid >> 5;
    const int rw  = w & 3;
    const int cw  = w >> 2;
    const int lane = tid & 31;
    const int gid = lane >> 2;
    const int q   = lane & 3;

    const int arow  = tid >> 1, ahalf = tid & 1;
    const int bn    = tid >> 2, bpart = tid & 3;
    const int grow  = (row0 + arow < cnt) ? g_rows[row0 + arow] : -1;

    const int aR = rw * 32 + (lane & 15);
    const int aC = (lane >> 4) * 8;
    const uint32_t addrAh = lds_addr(&sAh[aR][aC]);
    const uint32_t addrAl = lds_addr(&sAl[aR][aC]);
    const int bR = cw * 32 + ((lane >> 4) & 1) * 8 + (lane & 7);
    const int bC = ((lane >> 3) & 1) * 8;
    const uint32_t addrBh = lds_addr(&sBh[bR][bC]);
    const uint32_t addrBl = lds_addr(&sBl[bR][bC]);

    float acc[2][4][4];
    #pragma unroll
    for (int mt = 0; mt < 2; mt++)
        #pragma unroll
        for (int nt = 0; nt < 4; nt++)
            #pragma unroll
            for (int e = 0; e < 4; e++) acc[mt][nt][e] = 0.f;

    int k0 = 0;
    for (int it = 0; it < KPI / 32; ++it) {
        __syncthreads();
        {
            int kb = ahalf * 16;
            #pragma unroll
            for (int e = 0; e < 16; e++) {
                int k = k0 + kb + e;
                float v = (grow >= 0 && k < BF) ? A[(size_t)grow * BF + k] : 0.f;
                __nv_bfloat16 vh, vl;
                split_bf16(v, vh, vl);
                sAh[arow][kb + e] = vh;
                sAl[arow][kb + e] = vl;
            }
        }
        {
            const __nv_bfloat16* bBh = pWh + (size_t)(col0 + bn) * KPI + k0 + bpart * 8;
            const __nv_bfloat16* bBl = pWl + (size_t)(col0 + bn) * KPI + k0 + bpart * 8;
            *(uint4*)&sBh[bn][bpart * 8] = *(const uint4*)bBh;
            *(uint4*)&sBl[bn][bpart * 8] = *(const uint4*)bBl;
        }
        __syncthreads();
        #pragma unroll
        for (int ks = 0; ks < 2; ++ks) {
            const uint32_t ko = ks * 32;
            uint32_t afh[2][4], afl[2][4], bfh[2][4], bfl[2][4];
            #pragma unroll
            for (int mt = 0; mt < 2; mt++) {
                LDSM_X4(afh[mt], addrAh + mt * 1280 + ko);
                LDSM_X4(afl[mt], addrAl + mt * 1280 + ko);
            }
            #pragma unroll
            for (int p = 0; p < 2; p++) {
                LDSM_X4(bfh[p], addrBh + p * 1280 + ko);
                LDSM_X4(bfl[p], addrBl + p * 1280 + ko);
            }
            #pragma unroll
            for (int p = 0; p < 2; p++)
                #pragma unroll
                for (int s = 0; s < 2; s++) {
                    const int nt = 2 * p + s;
                    #pragma unroll
                    for (int mt = 0; mt < 2; mt++) {
                        MMA_BF16(acc[mt][nt], afh[mt], bfh[p][2 * s], bfh[p][2 * s + 1]);
                        MMA_BF16(acc[mt][nt], afh[mt], bfl[p][2 * s], bfl[p][2 * s + 1]);
                        MMA_BF16(acc[mt][nt], afl[mt], bfh[p][2 * s], bfh[p][2 * s + 1]);
                    }
                }
        }
        k0 += 32;
    }

    #pragma unroll
    for (int mt = 0; mt < 2; mt++) {
        #pragma unroll
        for (int rp = 0; rp < 2; rp++) {
            int lr = rw * 32 + mt * 16 + gid + rp * 8;
            int slot = row0 + lr;
            if (slot < cnt) {
                size_t row = g_rows[slot];
                #pragma unroll
                for (int nt = 0; nt < 4; nt++) {
                    int c = cw * 32 + nt * 8 + q * 2;
                    int h = col0 + c;
                    if (h < HH) {
                        float v0 = fmaxf(acc[mt][nt][rp * 2 + 0], 0.f);
                        float v1 = fmaxf(acc[mt][nt][rp * 2 + 1], 0.f);
                        *(float2*)&Co[row * HH + h] = make_float2(v0, v1);
                        __nv_bfloat16 h0, l0, h1, l1;
                        split_bf16(v0, h0, l0);
                        split_bf16(v1, h1, l1);
                        __nv_bfloat162 hp; hp.x = h0; hp.y = h1;
                        __nv_bfloat162 lp; lp.x = l0; lp.y = l1;
                        *(__nv_bfloat162*)&pH[row * KP + h] = hp;
                        *(__nv_bfloat162*)&pL[row * KP + h] = lp;
                    }
                }
            }
        }
    }
}

// ---------------------------------------------------------------------------
// f32x2 SGEMM (maW only): C = A @ W
// ---------------------------------------------------------------------------
#define BKg 12
template<int K>
__global__ __launch_bounds__(128, 3)
void k_gemm_f2(const float* __restrict__ A, const float* __restrict__ W,
               float* __restrict__ Co, int N) {
    const int row0 = blockIdx.y * 128;
    const int col0 = blockIdx.x * 64;
    __shared__ __align__(16) float As[BKg][132];
    __shared__ __align__(16) float Bs[BKg][72];
    const int tid = threadIdx.x;
    const int rg = tid >> 3;
    const int cg = tid & 7;

    int ar[3], ac4[3];
    #pragma unroll
    for (int q = 0; q < 3; q++) {
        int l = q * 128 + tid;
        ar[q]  = l / 3;
        ac4[q] = l - ar[q] * 3;
    }
    const int bk0  = tid >> 4;
    const int bk1  = (tid + 128) >> 4;
    const int bc4  = tid & 15;
    const bool hasB1  = (tid < 64);
    const bool bcolOK = (col0 + 4 * bc4 + 4 <= N);

    unsigned long long acc[8][4];
    #pragma unroll
    for (int i = 0; i < 8; i++)
        #pragma unroll
        for (int p = 0; p < 4; p++) acc[i][p] = 0ull;

    float4 ra[3], rb0, rb1;
    auto load_tile = [&](int k0) {
        #pragma unroll
        for (int q = 0; q < 3; q++)
            ra[q] = *(const float4*)&A[(size_t)(row0 + ar[q]) * K + k0 + 4 * ac4[q]];
        {
            int gk = k0 + bk0;
            rb0 = (gk < K && bcolOK) ? *(const float4*)&W[(size_t)gk * N + col0 + 4 * bc4]
                                     : make_float4(0.f, 0.f, 0.f, 0.f);
        }
        if (hasB1) {
            int gk = k0 + bk1;
            rb1 = (gk < K && bcolOK) ? *(const float4*)&W[(size_t)gk * N + col0 + 4 * bc4]
                                     : make_float4(0.f, 0.f, 0.f, 0.f);
        }
    };

    const int nIter = (K + BKg - 1) / BKg;
    load_tile(0);
    int k0 = 0;
    for (int it = 0; it < nIter; ++it) {
        __syncthreads();
        #pragma unroll
        for (int q = 0; q < 3; q++) {
            int kb = 4 * ac4[q];
            As[kb + 0][ar[q]] = ra[q].x;
            As[kb + 1][ar[q]] = ra[q].y;
            As[kb + 2][ar[q]] = ra[q].z;
            As[kb + 3][ar[q]] = ra[q].w;
        }
        *(float4*)&Bs[bk0][4 * bc4] = rb0;
        if (hasB1) *(float4*)&Bs[bk1][4 * bc4] = rb1;
        __syncthreads();
        if (it + 1 < nIter) load_tile(k0 + BKg);
        #pragma unroll
        for (int kk = 0; kk < BKg; ++kk) {
            float4 a0 = *(const float4*)&As[kk][rg * 8];
            float4 a1 = *(const float4*)&As[kk][rg * 8 + 4];
            ulonglong2 b01 = *(const ulonglong2*)&Bs[kk][cg * 8];
            ulonglong2 b23 = *(const ulonglong2*)&Bs[kk][cg * 8 + 4];
            float av[8] = {a0.x, a0.y, a0.z, a0.w, a1.x, a1.y, a1.z, a1.w};
            #pragma unroll
            for (int i = 0; i < 8; i++) {
                unsigned long long ap = pack2(av[i], av[i]);
                ffma2(acc[i][0], ap, b01.x);
                ffma2(acc[i][1], ap, b01.y);
                ffma2(acc[i][2], ap, b23.x);
                ffma2(acc[i][3], ap, b23.y);
            }
        }
        k0 += BKg;
    }

    const bool fastcol = (col0 + 64 <= N);
    #pragma unroll
    for (int i = 0; i < 8; i++) {
        size_t row = row0 + rg * 8 + i;
        float v[8];
        #pragma unroll
        for (int p = 0; p < 4; p++) {
            float2 f = unpack2(acc[i][p]);
            v[2 * p] = f.x; v[2 * p + 1] = f.y;
        }
        size_t base = row * N + col0 + cg * 8;
        if (fastcol) {
            *(float4*)&Co[base]     = make_float4(v[0], v[1], v[2], v[3]);
            *(float4*)&Co[base + 4] = make_float4(v[4], v[5], v[6], v[7]);
        } else {
            #pragma unroll
            for (int jj = 0; jj < 8; jj++)
                if (col0 + cg * 8 + jj < N) Co[base + jj] = v[jj];
        }
    }
}

// ---------------------------------------------------------------------------
// Compacted-row mma.sync GEMM (step 0 only): Cc[slot,:] = prev@W
// ---------------------------------------------------------------------------
__global__ __launch_bounds__(256)
void k_gemmc_mma(const __nv_bfloat16* __restrict__ pAh, const __nv_bfloat16* __restrict__ pAl,
                 const __nv_bfloat16* __restrict__ pWh, const __nv_bfloat16* __restrict__ pWl,
                 float* __restrict__ Cc) {
    extern __shared__ __align__(16) char smraw[];
    __nv_bfloat16 (*sAh)[40] = (__nv_bfloat16(*)[40])(smraw + 0);
    __nv_bfloat16 (*sAl)[40] = (__nv_bfloat16(*)[40])(smraw + 10240);
    __nv_bfloat16 (*sBh)[40] = (__nv_bfloat16(*)[40])(smraw + 20480);
    __nv_bfloat16 (*sBl)[40] = (__nv_bfloat16(*)[40])(smraw + 25600);

    const int cnt = g_cnt;
    const int row0 = blockIdx.y * 128;
    if (row0 >= cnt) return;
    const int col0 = blockIdx.x * 64;
    const int tid = threadIdx.x;
    const int w   = tid >> 5;
    const int rw  = w & 3;
    const int cw  = w >> 2;
    const int lane = tid & 31;
    const int gid = lane >> 2;
    const int q   = lane & 3;

    const int arow  = tid >> 1, apart = tid & 1;
    const int bn    = tid >> 2, bpart = tid & 3;
    const int grow  = (row0 + arow < cnt) ? g_rows[row0 + arow] : -1;

    const int aR = rw * 32 + (lane & 15);
    const int aC = (lane >> 4) * 8;
    const uint32_t addrAh = lds_addr(&sAh[aR][aC]);
    const uint32_t addrAl = lds_addr(&sAl[aR][aC]);
    const int bR = cw * 32 + ((lane >> 4) & 1) * 8 + (lane & 7);
    const int bC = ((lane >> 3) & 1) * 8;
    const uint32_t addrBh = lds_addr(&sBh[bR][bC]);
    const uint32_t addrBl = lds_addr(&sBl[bR][bC]);

    float acc[2][4][4];
    #pragma unroll
    for (int mt = 0; mt < 2; mt++)
        #pragma unroll
        for (int nt = 0; nt < 4; nt++)
            #pragma unroll
            for (int e = 0; e < 4; e++) acc[mt][nt][e] = 0.f;

    uint4 rAh[2], rAl[2], rBh, rBl;
    auto load_tile = [&](int k0) {
        if (grow >= 0) {
            const __nv_bfloat16* bAh = pAh + (size_t)grow * KP + k0 + apart * 16;
            const __nv_bfloat16* bAl = pAl + (size_t)grow * KP + k0 + apart * 16;
            rAh[0] = *(const uint4*)bAh;  rAh[1] = *(const uint4*)(bAh + 8);
            rAl[0] = *(const uint4*)bAl;  rAl[1] = *(const uint4*)(bAl + 8);
        } else {
            rAh[0] = rAh[1] = rAl[0] = rAl[1] = make_uint4(0, 0, 0, 0);
        }
        const __nv_bfloat16* bBh = pWh + (size_t)(col0 + bn) * KP + k0 + bpart * 8;
        const __nv_bfloat16* bBl = pWl + (size_t)(col0 + bn) * KP + k0 + bpart * 8;
        rBh = *(const uint4*)bBh;
        rBl = *(const uint4*)bBl;
    };

    load_tile(0);
    int k0 = 0;
    for (int it = 0; it < KP / 32; ++it) {
        __syncthreads();
        *(uint4*)&sAh[arow][apart * 16]     = rAh[0];
        *(uint4*)&sAh[arow][apart * 16 + 8] = rAh[1];
        *(uint4*)&sAl[arow][apart * 16]     = rAl[0];
        *(uint4*)&sAl[arow][apart * 16 + 8] = rAl[1];
        *(uint4*)&sBh[bn][bpart * 8] = rBh;
        *(uint4*)&sBl[bn][bpart * 8] = rBl;
        __syncthreads();
        if (it + 1 < KP / 32) load_tile(k0 + 32);
        #pragma unroll
        for (int ks = 0; ks < 2; ++ks) {
            const uint32_t ko = ks * 32;
            uint32_t afh[2][4], afl[2][4], bfh[2][4], bfl[2][4];
            #pragma unroll
            for (int mt = 0; mt < 2; mt++) {
                LDSM_X4(afh[mt], addrAh + mt * 1280 + ko);
                LDSM_X4(afl[mt], addrAl + mt * 1280 + ko);
            }
            #pragma unroll
            for (int p = 0; p < 2; p++) {
                LDSM_X4(bfh[p], addrBh + p * 1280 + ko);
                LDSM_X4(bfl[p], addrBl + p * 1280 + ko);
            }
            #pragma unroll
            for (int p = 0; p < 2; p++)
                #pragma unroll
                for (int s = 0; s < 2; s++) {
                    const int nt = 2 * p + s;
                    #pragma unroll
                    for (int mt = 0; mt < 2; mt++) {
                        MMA_BF16(acc[mt][nt], afh[mt], bfh[p][2 * s], bfh[p][2 * s + 1]);
                        MMA_BF16(acc[mt][nt], afh[mt], bfl[p][2 * s], bfl[p][2 * s + 1]);
                        MMA_BF16(acc[mt][nt], afl[mt], bfh[p][2 * s], bfh[p][2 * s + 1]);
                    }
                }
        }
        k0 += 32;
    }

    #pragma unroll
    for (int mt = 0; mt < 2; mt++) {
        #pragma unroll
        for (int rp = 0; rp < 2; rp++) {
            int lr = rw * 32 + mt * 16 + gid + rp * 8;
            int slot = row0 + lr;
            if (slot < cnt) {
                #pragma unroll
                for (int nt = 0; nt < 4; nt++) {
                    int c = cw * 32 + nt * 8 + q * 2;
                    int h = col0 + c;
                    if (h < HH) {
                        *(float2*)&Cc[(size_t)slot * HH + h] =
                            make_float2(acc[mt][nt][rp * 2 + 0], acc[mt][nt][rp * 2 + 1]);
                    }
                }
            }
        }
    }
}

// ---------------------------------------------------------------------------
// Step-0 epilogue, float2-vectorized (round-15):
// thread covers cols {2*tid, 2*tid+1} and (tid<22) {2*tid+256, 2*tid+257}.
// Same i-loop reduction order as round 13/14 -> bit-identical results.
// ---------------------------------------------------------------------------
__global__ void k_epilogue0(const float* __restrict__ ib, const float* __restrict__ maW,
                            const float* __restrict__ Cc, const float* __restrict__ adj,
                            __nv_bfloat16* __restrict__ pOh, __nv_bfloat16* __restrict__ pOl) {
    int gj = blockIdx.x;
    int g = gj >> 6, j = gj & 63;
    __shared__ float adjT[64], smv[64];
    __shared__ int   slots[64];
    int tid = threadIdx.x;        // 128
    if (tid < 64) {
        adjT[tid]  = adj[((size_t)(g * 64 + j)) * 64 + tid];
        smv[tid]   = g_sm[((size_t)(g * 64 + tid)) * 64 + j];
        slots[tid] = g_slot[((size_t)(g * 64 + j)) * 64 + tid];
    }
    __syncthreads();
    const int h0 = 2 * tid;              // 0..254
    const int h1 = 2 * tid + 256;        // 256..298 (tid < 22)
    const bool has1 = (tid < 22);
    float2 s0 = make_float2(0.f, 0.f), s1 = make_float2(0.f, 0.f);
    float2 m0 = make_float2(-INFINITY, -INFINITY);
    float2 m1 = make_float2(-INFINITY, -INFINITY);
    for (int i = 0; i < 64; ++i) {
        size_t rowOut = ((size_t)(g * 64 + i) * 64 + j);
        size_t obase  = rowOut * HH;
        size_t pbase  = rowOut * KP;
        size_t rowM   = (size_t)(g * 64 + i) * HH;
        int slot = slots[i];
        float a = adjT[i], wv = smv[i];
        {
            float2 ibv = *(const float2*)&ib[obase + h0];
            float2 mw  = *(const float2*)&maW[rowM + h0];
            float2 cv  = (slot >= 0) ? *(const float2*)&Cc[(size_t)slot * HH + h0]
                                     : make_float2(0.f, 0.f);
            float v0 = fmaxf(ibv.x + a * mw.x - cv.x, 0.f) * wv;
            float v1 = fmaxf(ibv.y + a * mw.y - cv.y, 0.f) * wv;
            __nv_bfloat16 vh0, vl0, vh1, vl1;
            split_bf16(v0, vh0, vl0);
            split_bf16(v1, vh1, vl1);
            __nv_bfloat162 hp; hp.x = vh0; hp.y = vh1;
            __nv_bfloat162 lp; lp.x = vl0; lp.y = vl1;
            *(__nv_bfloat162*)&pOh[pbase + h0] = hp;
            *(__nv_bfloat162*)&pOl[pbase + h0] = lp;
            s0.x += v0;  s0.y += v1;
            m0.x = fmaxf(m0.x, v0);  m0.y = fmaxf(m0.y, v1);
        }
        if (has1) {
            float2 ibv = *(const float2*)&ib[obase + h1];
            float2 mw  = *(const float2*)&maW[rowM + h1];
            float2 cv  = (slot >= 0) ? *(const float2*)&Cc[(size_t)slot * HH + h1]
                                     : make_float2(0.f, 0.f);
            float v0 = fmaxf(ibv.x + a * mw.x - cv.x, 0.f) * wv;
            float v1 = fmaxf(ibv.y + a * mw.y - cv.y, 0.f) * wv;
            __nv_bfloat16 vh0, vl0, vh1, vl1;
            split_bf16(v0, vh0, vl0);
            split_bf16(v1, vh1, vl1);
            __nv_bfloat162 hp; hp.x = vh0; hp.y = vh1;
            __nv_bfloat162 lp; lp.x = vl0; lp.y = vl1;
            *(__nv_bfloat162*)&pOh[pbase + h1] = hp;
            *(__nv_bfloat162*)&pOl[pbase + h1] = lp;
            s1.x += v0;  s1.y += v1;
            m1.x = fmaxf(m1.x, v0);  m1.y = fmaxf(m1.y, v1);
        }
    }
    {
        size_t base = (size_t)(g * 64 + j) * HH;
        float2 cur = *(float2*)&g_msg_atom[base + h0];
        cur.x += s0.x * (1.f / (1.f + expf(-m0.x)));
        cur.y += s0.y * (1.f / (1.f + expf(-m0.y)));
        *(float2*)&g_msg_atom[base + h0] = cur;
        if (has1) {
            float2 c1 = *(float2*)&g_msg_atom[base + h1];
            c1.x += s1.x * (1.f / (1.f + expf(-m1.x)));
            c1.y += s1.y * (1.f / (1.f + expf(-m1.y)));
            *(float2*)&g_msg_atom[base + h1] = c1;
        }
    }
}

// ---------------------------------------------------------------------------
// Tensor-core fused bond step — round-8/11 version (used for step 1).
// ---------------------------------------------------------------------------
template<int UPDATE, int EMIT, int STORE>
__global__ __launch_bounds__(256)
void k_bondstep_mma(const __nv_bfloat16* __restrict__ pAh, const __nv_bfloat16* __restrict__ pAl,
                    const __nv_bfloat16* __restrict__ pWh, const __nv_bfloat16* __restrict__ pWl,
                    const float* __restrict__ ib, const float* __restrict__ maW,
                    const float* __restrict__ adj, float* __restrict__ mbout,
                    __nv_bfloat16* __restrict__ pOh, __nv_bfloat16* __restrict__ pOl) {
    extern __shared__ __align__(16) char smraw[];
    __nv_bfloat16 (*sAh)[40] = (__nv_bfloat16(*)[40])(smraw + 0);
    __nv_bfloat16 (*sAl)[40] = (__nv_bfloat16(*)[40])(smraw + 10240);
    __nv_bfloat16 (*sBh)[40] = (__nv_bfloat16(*)[40])(smraw + 20480);
    __nv_bfloat16 (*sBl)[40] = (__nv_bfloat16(*)[40])(smraw + 25600);
    float (*maWs)[68]        = (float(*)[68])(smraw + 30720);
    float (*psum)[65]        = (float(*)[65])(smraw + 48128);
    float (*pmax)[65]        = (float(*)[65])(smraw + 56448);
    float (*adjs)[64]        = (float(*)[64])(smraw + 64768);
    float (*smvv)[64]        = (float(*)[64])(smraw + 65280);

    const int row0 = blockIdx.y * 128;
    const int col0 = blockIdx.x * 64;
    const int g  = row0 >> 12;
    const int x0 = (row0 >> 6) & 63;
    const int tid = threadIdx.x;
    const int w   = tid >> 5;
    const int rw  = w & 3;
    const int cw  = w >> 2;
    const int lane = tid & 31;
    const int gid = lane >> 2;
    const int q   = lane & 3;

    if (tid < 128) {
        int xl = tid >> 6, y = tid & 63;
        adjs[xl][y] = adj[(size_t)(g * 64 + x0 + xl) * 64 + y];
        smvv[xl][y] = g_sm[(size_t)(g * 64 + y) * 64 + x0 + xl];
    }
    for (int l = tid; l < 64 * 16; l += 256) {
        int y = l >> 4, c4 = (l & 15) * 4;
        int c = col0 + c4;
        float4 v;
        if (c + 4 <= HH) v = *(const float4*)&maW[(size_t)(g * 64 + y) * HH + c];
        else {
            float t[4];
            #pragma unroll
            for (int e = 0; e < 4; e++)
                t[e] = (c + e < HH) ? maW[(size_t)(g * 64 + y) * HH + c + e] : 0.f;
            v = make_float4(t[0], t[1], t[2], t[3]);
        }
        *(float4*)&maWs[y][c4] = v;
    }

    const int arow  = tid >> 1, apart = tid & 1;
    const int bn    = tid >> 2, bpart = tid & 3;

    const int aR = rw * 32 + (lane & 15);
    const int aC = (lane >> 4) * 8;
    const uint32_t addrAh = lds_addr(&sAh[aR][aC]);
    const uint32_t addrAl = lds_addr(&sAl[aR][aC]);
    const int bR = cw * 32 + ((lane >> 4) & 1) * 8 + (lane & 7);
    const int bC = ((lane >> 3) & 1) * 8;
    const uint32_t addrBh = lds_addr(&sBh[bR][bC]);
    const uint32_t addrBl = lds_addr(&sBl[bR][bC]);

    float acc[2][4][4];
    #pragma unroll
    for (int mt = 0; mt < 2; mt++)
        #pragma unroll
        for (int nt = 0; nt < 4; nt++)
            #pragma unroll
            for (int e = 0; e < 4; e++) acc[mt][nt][e] = 0.f;

    uint4 rAh[2], rAl[2], rBh, rBl;
    auto load_tile = [&](int k0) {
        const __nv_bfloat16* bAh = pAh + (size_t)(row0 + arow) * KP + k0 + apart * 16;
        const __nv_bfloat16* bAl = pAl + (size_t)(row0 + arow) * KP + k0 + apart * 16;
        rAh[0] = *(const uint4*)bAh;  rAh[1] = *(const uint4*)(bAh + 8);
        rAl[0] = *(const uint4*)bAl;  rAl[1] = *(const uint4*)(bAl + 8);
        const __nv_bfloat16* bBh = pWh + (size_t)(col0 + bn) * KP + k0 + bpart * 8;
        const __nv_bfloat16* bBl = pWl + (size_t)(col0 + bn) * KP + k0 + bpart * 8;
        rBh = *(const uint4*)bBh;
        rBl = *(const uint4*)bBl;
    };

    load_tile(0);
    int k0 = 0;
    for (int it = 0; it < KP / 32; ++it) {
        __syncthreads();
        *(uint4*)&sAh[arow][apart * 16]     = rAh[0];
        *(uint4*)&sAh[arow][apart * 16 + 8] = rAh[1];
        *(uint4*)&sAl[arow][apart * 16]     = rAl[0];
        *(uint4*)&sAl[arow][apart * 16 + 8] = rAl[1];
        *(uint4*)&sBh[bn][bpart * 8] = rBh;
        *(uint4*)&sBl[bn][bpart * 8] = rBl;
        __syncthreads();
        if (it + 1 < KP / 32) load_tile(k0 + 32);
        #pragma unroll
        for (int ks = 0; ks < 2; ++ks) {
            const uint32_t ko = ks * 32;
            uint32_t afh[2][4], afl[2][4], bfh[2][4], bfl[2][4];
            #pragma unroll
            for (int mt = 0; mt < 2; mt++) {
                LDSM_X4(afh[mt], addrAh + mt * 1280 + ko);
                LDSM_X4(afl[mt], addrAl + mt * 1280 + ko);
            }
            #pragma unroll
            for (int p = 0; p < 2; p++) {
                LDSM_X4(bfh[p], addrBh + p * 1280 + ko);
                LDSM_X4(bfl[p], addrBl + p * 1280 + ko);
            }
            #pragma unroll
            for (int p = 0; p < 2; p++)
                #pragma unroll
                for (int s = 0; s < 2; s++) {
                    const int nt = 2 * p + s;
                    #pragma unroll
                    for (int mt = 0; mt < 2; mt++) {
                        MMA_BF16(acc[mt][nt], afh[mt], bfh[p][2 * s], bfh[p][2 * s + 1]);
                        MMA_BF16(acc[mt][nt], afh[mt], bfl[p][2 * s], bfl[p][2 * s + 1]);
                        MMA_BF16(acc[mt][nt], afl[mt], bfh[p][2 * s], bfh[p][2 * s + 1]);
                    }
                }
        }
        k0 += 32;
    }

    float tsum[4][2], tmax[4][2];
    #pragma unroll
    for (int nt = 0; nt < 4; nt++)
        #pragma unroll
        for (int p = 0; p < 2; p++) { tsum[nt][p] = 0.f; tmax[nt][p] = -INFINITY; }

    #pragma unroll
    for (int mt = 0; mt < 2; mt++) {
        #pragma unroll
        for (int rp = 0; rp < 2; rp++) {
            int lr = rw * 32 + mt * 16 + gid + rp * 8;
            int xl = lr >> 6, y = lr & 63;
            int x  = x0 + xl;
            float a = adjs[xl][y];
            float wv = smvv[xl][y];
            size_t brow = (size_t)(g * 64 + y) * 64 + x;
            #pragma unroll
            for (int nt = 0; nt < 4; nt++) {
                int c = cw * 32 + nt * 8 + q * 2;
                int h = col0 + c;
                if (h < HH) {
                    size_t ob = brow * HH + h;
                    float2 ibv = *(const float2*)&ib[ob];
                    float v0 = fmaxf(ibv.x + a * maWs[y][c]     - acc[mt][nt][rp * 2 + 0], 0.f) * wv;
                    float v1 = fmaxf(ibv.y + a * maWs[y][c + 1] - acc[mt][nt][rp * 2 + 1], 0.f) * wv;
                    if (STORE) *(float2*)&mbout[ob] = make_float2(v0, v1);
                    if (EMIT) {
                        __nv_bfloat16 h0, l0, h1, l1;
                        split_bf16(v0, h0, l0);
                        split_bf16(v1, h1, l1);
                        size_t pb = brow * KP + h;
                        __nv_bfloat162 hp; hp.x = h0; hp.y = h1;
                        __nv_bfloat162 lp; lp.x = l0; lp.y = l1;
                        *(__nv_bfloat162*)&pOh[pb] = hp;
                        *(__nv_bfloat162*)&pOl[pb] = lp;
                    }
                    tsum[nt][0] += v0;  tmax[nt][0] = fmaxf(tmax[nt][0], v0);
                    tsum[nt][1] += v1;  tmax[nt][1] = fmaxf(tmax[nt][1], v1);
                }
            }
        }
    }
    {
        int slot = rw * 8 + gid;
        #pragma unroll
        for (int nt = 0; nt < 4; nt++) {
            int c = cw * 32 + nt * 8 + q * 2;
            psum[slot][c]     = tsum[nt][0];
            psum[slot][c + 1] = tsum[nt][1];
            pmax[slot][c]     = tmax[nt][0];
            pmax[slot][c + 1] = tmax[nt][1];
        }
    }
    __syncthreads();
    if (tid < 128) {
        int xl = tid >> 6, c = tid & 63;
        if (col0 + c < HH) {
            float s = 0.f, m = -INFINITY;
            #pragma unroll
            for (int r = 0; r < 16; r++) {
                s += psum[xl * 16 + r][c];
                m = fmaxf(m, pmax[xl * 16 + r][c]);
            }
            float aggv = s * (1.f / (1.f + expf(-m)));
            size_t idx = (size_t)(g * 64 + x0 + xl) * HH + col0 + c;
            if (UPDATE) g_msg_atom[idx] += aggv;
            else        g_agg[idx] = aggv;
        }
    }
}

// ---------------------------------------------------------------------------
// input_atom = relu(f_atoms @ W_i_atom) (also -> msg_atom)
// ---------------------------------------------------------------------------
__global__ void k_input_atom(const float* __restrict__ A, const float* __restrict__ W) {
    const int row0 = blockIdx.y * 64;
    const int col0 = blockIdx.x * 64;
    __shared__ float As[16][68];
    __shared__ float Bs[16][68];
    const int tid = threadIdx.x;
    const int tx = tid & 15, ty = tid >> 4;
    float acc[4][4] = {};
    for (int k0 = 0; k0 < AF; k0 += 16) {
        __syncthreads();
        {
            int kk = tid & 15;
            int k  = k0 + kk;
            #pragma unroll
            for (int qq = 0; qq < 4; qq++) {
                int r = (tid >> 4) + qq * 16;
                As[kk][r] = (k < AF) ? A[(row0 + r) * AF + k] : 0.f;
            }
        }
        {
            int nn = tid & 63;
            int c  = col0 + nn;
            #pragma unroll
            for (int qq = 0; qq < 4; qq++) {
                int kk = (tid >> 6) + qq * 4;
                int k  = k0 + kk;
                Bs[kk][nn] = (k < AF && c < HH) ? W[k * HH + c] : 0.f;
            }
        }
        __syncthreads();
        #pragma unroll
        for (int kk = 0; kk < 16; kk++) {
            float4 a4 = *(const float4*)&As[kk][ty * 4];
            float4 b4 = *(const float4*)&Bs[kk][tx * 4];
            float a[4] = {a4.x, a4.y, a4.z, a4.w};
            float b[4] = {b4.x, b4.y, b4.z, b4.w};
            #pragma unroll
            for (int i = 0; i < 4; i++)
                #pragma unroll
                for (int j = 0; j < 4; j++)
                    acc[i][j] += a[i] * b[j];
        }
    }
    #pragma unroll
    for (int i = 0; i < 4; i++) {
        int r = row0 + ty * 4 + i;
        #pragma unroll
        for (int j = 0; j < 4; j++) {
            int c = col0 + tx * 4 + j;
            if (c < HH) {
                float v = acc[i][j];
                v = v > 0.f ? v : 0.f;
                g_input_atom[r * HH + c] = v;
                g_msg_atom[r * HH + c]   = v;
            }
        }
    }
}

// ---------------------------------------------------------------------------
// agg over input_bond with adjacency skip — float2-vectorized (round-15).
// 160 threads; thread covers cols {2*tid, 2*tid+1} (tid < 150).
// Same n-loop reduction order -> bit-identical results.
// ---------------------------------------------------------------------------
__global__ void k_agg(const float* __restrict__ mb, const float* __restrict__ adj) {
    int gm = blockIdx.x;
    int g = gm >> 6, m = gm & 63;
    __shared__ float adjc[64];
    int tid = threadIdx.x;       // 160
    if (tid < 64) adjc[tid] = adj[(size_t)(g * 64 + tid) * 64 + m];
    __syncthreads();
    int h = 2 * tid;
    if (h >= HH) return;
    const float* base = mb + ((size_t)(g * 64) * 64 + m) * HH + h;
    float2 s = make_float2(0.f, 0.f);
    float2 mx = make_float2(0.f, 0.f);
    for (int n = 0; n < 64; n++) {
        if (adjc[n] != 0.f) {
            float2 v = *(const float2*)&base[(size_t)n * 64 * HH];
            s.x += v.x;  s.y += v.y;
            mx.x = fmaxf(mx.x, v.x);  mx.y = fmaxf(mx.y, v.y);
        }
    }
    size_t idx = (size_t)gm * HH + h;
    float2 cur = *(float2*)&g_msg_atom[idx];
    cur.x += s.x * (1.f / (1.f + expf(-mx.x)));
    cur.y += s.y * (1.f / (1.f + expf(-mx.y)));
    *(float2*)&g_msg_atom[idx] = cur;
}

// ---------------------------------------------------------------------------
// Resonance + softmax, 4 column-tiles per graph (128 blocks).
// ---------------------------------------------------------------------------
__global__ void k_resonance4(const float* __restrict__ adj) {
    int g  = blockIdx.x >> 2;
    int qt = blockIdx.x & 3;
    __shared__ float mt[64][101];
    __shared__ float rr[64][17];
    int tid = threadIdx.x;
    int tx = tid & 15;
    int ty = tid >> 4;
    float acc[4] = {};
    for (int c = 0; c < 3; ++c) {
        __syncthreads();
        for (int l = tid; l < 6400; l += 256) {
            int r = l / 100, k = l - r * 100;
            mt[r][k] = g_msg_atom[((size_t)(g * 64 + r)) * 300 + c * 100 + k];
        }
        __syncthreads();
        for (int kk = 0; kk < 100; ++kk) {
            float b = mt[qt * 16 + tx][kk];
            #pragma unroll
            for (int i = 0; i < 4; i++)
                acc[i] += mt[ty * 4 + i][kk] * b;
        }
    }
    #pragma unroll
    for (int i = 0; i < 4; i++)
        rr[ty * 4 + i][tx] = acc[i];
    __syncthreads();
    if (tid < 16) {
        int m = qt * 16 + tid;
        float mxv = -INFINITY;
        for (int n = 0; n < 64; n++) {
            float v = rr[n][tid] * adj[((size_t)(g * 64 + n)) * 64 + m];
            rr[n][tid] = v;
            mxv = fmaxf(mxv, v);
        }
        float sum = 0.f;
        for (int n = 0; n < 64; n++) {
            float e = expf(rr[n][tid] - mxv);
            rr[n][tid] = e;
            sum += e;
        }
        float inv = 1.f / sum;
        for (int n = 0; n < 64; n++)
            g_sm[(size_t)(g * 64 + n) * 64 + m] = rr[n][tid] * inv;
    }
}

// ---------------------------------------------------------------------------
__global__ void k_output(const float* __restrict__ W, const float* __restrict__ bias,
                         float* __restrict__ out) {
    const int row0 = blockIdx.y * 64;
    const int col0 = blockIdx.x * 64;
    __shared__ float As[16][68];
    __shared__ float Bs[16][68];
    const int tid = threadIdx.x;
    const int tx = tid & 15, ty = tid >> 4;
    float acc[4][4] = {};
    for (int k0 = 0; k0 < 900; k0 += 16) {
        __syncthreads();
        {
            int kk = tid & 15;
            int k  = k0 + kk;
            #pragma unroll
            for (int qq = 0; qq < 4; qq++) {
                int r = (tid >> 4) + qq * 16;
                int row = row0 + r;
                float v = 0.f;
                if (k < 900) {
                    if (k < 300)       v = g_agg[row * HH + k];
                    else if (k < 600)  v = g_msg_atom[row * HH + (k - 300)];
                    else               v = g_input_atom[row * HH + (k - 600)];
                }
                As[kk][r] = v;
            }
        }
        {
            int nn = tid & 63;
            int c  = col0 + nn;
            #pragma unroll
            for (int qq = 0; qq < 4; qq++) {
                int kk = (tid >> 6) + qq * 4;
                int k  = k0 + kk;
                Bs[kk][nn] = (k < 900 && c < HH) ? W[k * HH + c] : 0.f;
            }
        }
        __syncthreads();
        #pragma unroll
        for (int kk = 0; kk < 16; kk++) {
            float4 a4 = *(const float4*)&As[kk][ty * 4];
            float4 b4 = *(const float4*)&Bs[kk][tx * 4];
            float a[4] = {a4.x, a4.y, a4.z, a4.w};
            float b[4] = {b4.x, b4.y, b4.z, b4.w};
            #pragma unroll
            for (int i = 0; i < 4; i++)
                #pragma unroll
                for (int j = 0; j < 4; j++)
                    acc[i][j] += a[i] * b[j];
        }
    }
    #pragma unroll
    for (int i = 0; i < 4; i++) {
        int r = row0 + ty * 4 + i;
        #pragma unroll
        for (int j = 0; j < 4; j++) {
            int c = col0 + tx * 4 + j;
            if (c < HH) {
                float v = acc[i][j] + bias[c];
                out[r * HH + c] = v > 0.f ? v : 0.f;
            }
        }
    }
}

// ---------------------------------------------------------------------------
extern "C" void kernel_launch(void* const* d_in, const int* in_sizes, int n_in,
                              void* d_out, int out_size) {
    const float* f_atoms  = (const float*)d_in[0];
    const float* f_bonds  = (const float*)d_in[1];
    const float* adj      = (const float*)d_in[2];
    const float* W_i_atom = (const float*)d_in[3];
    const float* W_i_bond = (const float*)d_in[4];
    const float* W_h0     = (const float*)d_in[5];
    const float* W_h1     = (const float*)d_in[6];
    const float* W_o      = (const float*)d_in[7];
    const float* b_o      = (const float*)d_in[8];
    float* out = (float*)d_out;

    float *p_inbond = 0, *p_mbB = 0, *p_msg = 0, *p_maW = 0, *p_Cc = 0;
    __nv_bfloat16 *p0h = 0, *p0l = 0, *p1h = 0, *p1l = 0;
    __nv_bfloat16 *wt0h = 0, *wt0l = 0, *wt1h = 0, *wt1l = 0, *wtih = 0, *wtil = 0;
    cudaGetSymbolAddress((void**)&p_inbond, g_input_bond);
    cudaGetSymbolAddress((void**)&p_mbB, g_mbB);
    cudaGetSymbolAddress((void**)&p_msg, g_msg_atom);
    cudaGetSymbolAddress((void**)&p_maW, g_maW);
    cudaGetSymbolAddress((void**)&p_Cc, g_Cc);
    cudaGetSymbolAddress((void**)&p0h, g_P0h);
    cudaGetSymbolAddress((void**)&p0l, g_P0l);
    cudaGetSymbolAddress((void**)&p1h, g_P1h);
    cudaGetSymbolAddress((void**)&p1l, g_P1l);
    cudaGetSymbolAddress((void**)&wt0h, g_Wt0h);
    cudaGetSymbolAddress((void**)&wt0l, g_Wt0l);
    cudaGetSymbolAddress((void**)&wt1h, g_Wt1h);
    cudaGetSymbolAddress((void**)&wt1l, g_Wt1l);
    cudaGetSymbolAddress((void**)&wtih, g_WtIh);
    cudaGetSymbolAddress((void**)&wtil, g_WtIl);

    float* mb_final = (out_size >= AR * HH + BR * HH) ? (out + AR * HH) : p_mbB;

    const int SMEM_MMA = 66560;
    const int SMEM_GC  = 30720;
    cudaFuncSetAttribute(k_bondstep_mma<0, 0, 1>,
                         cudaFuncAttributeMaxDynamicSharedMemorySize, SMEM_MMA);
    cudaFuncSetAttribute(k_gemmc_mma,
                         cudaFuncAttributeMaxDynamicSharedMemorySize, SMEM_GC);
    cudaFuncSetAttribute(k_inbond_mma,
                         cudaFuncAttributeMaxDynamicSharedMemorySize, SMEM_GC);

    // sparsity compaction (adj binary, ~30% dense) + slot map
    k_reset<<<1, 32>>>();
    k_compact<<<(BR + 255) / 256, 256>>>(adj);

    k_input_atom<<<dim3(5, 32), 256>>>(f_atoms, W_i_atom);
    k_convW<<<HH, KP>>>(W_h0, wt0h, wt0l);
    k_convW<<<HH, KP>>>(W_h1, wt1h, wt1l);
    k_convWi<<<HH, KPI>>>(W_i_bond, wtih, wtil);
    // input_bond over nonzero rows only via tensor cores (fp32 ib + P0 planes)
    k_inbond_mma<<<dim3(5, BR / 128), 256, SMEM_GC>>>(f_bonds, wtih, wtil,
                                                      p_inbond, p0h, p0l);

    // ---- depth step 0 (prev = input_bond, 70% zero rows -> compacted GEMM) ----
    k_agg<<<2048, 160>>>(p_inbond, adj);
    k_resonance4<<<128, 256>>>(adj);
    k_gemm_f2<HH><<<dim3(5, AR / 128), 128>>>(p_msg, W_h0, p_maW, HH);
    k_gemmc_mma<<<dim3(5, BR / 128), 256, SMEM_GC>>>(p0h, p0l, wt0h, wt0l, p_Cc);
    k_epilogue0<<<2048, 128>>>(p_inbond, p_maW, p_Cc, adj, p1h, p1l);

    // ---- depth step 1 (prev = mb1 planes, dense) ----
    k_resonance4<<<128, 256>>>(adj);
    k_gemm_f2<HH><<<dim3(5, AR / 128), 128>>>(p_msg, W_h1, p_maW, HH);
    k_bondstep_mma<0, 0, 1><<<dim3(5, BR / 128), 256, SMEM_MMA>>>(
        p1h, p1l, wt1h, wt1l, p_inbond, p_maW, adj, mb_final, nullptr, nullptr);

    // ---- readout ----
    k_output<<<dim3(5, 32), 256>>>(W_o, b_o, out);
}

// round 16
// speedup vs baseline: 1.0740x; 1.0740x over previous
#include <cuda_runtime.h>
#include <cuda_bf16.h>
#include <math.h>
#include <stdint.h>

// Problem constants
#define GG 32
#define NA 64
#define HH 300
#define AF 133
#define BF 147
#define AR (GG*NA)     // 2048
#define BR (GG*NA*NA)  // 131072
#define KP 320         // padded K for bond-step planes (cols [300,320) stay zero)
#define KPI 160        // padded K for input_bond GEMM (BF=147 -> 160)
#define NIT_KP 10      // KP/32 mainloop iterations; last iteration: ks=0 only (K<=304)

// Scratch (zero-initialized device globals; allocation-free)
__device__ float g_input_atom[AR*HH];
__device__ float g_msg_atom[AR*HH];
__device__ float g_agg[AR*HH];
__device__ float g_maW[AR*HH];
__device__ float g_input_bond[BR*HH];   // 157 MB fp32 (zero rows stay zero-init)
__device__ float g_mbB[BR*HH];          // fallback mb_final
__device__ float g_Cc[(size_t)BR*HH];   // compacted C = prev@W (step 0)
__device__ float g_sm[BR];
__device__ int   g_cnt;
__device__ int   g_rows[BR];
__device__ int   g_slot[BR];
// bf16 hi/lo planes (pads + zero rows never written -> stay zero)
__device__ __nv_bfloat16 g_P0h[(size_t)BR*KP];
__device__ __nv_bfloat16 g_P0l[(size_t)BR*KP];
__device__ __nv_bfloat16 g_P1h[(size_t)BR*KP];
__device__ __nv_bfloat16 g_P1l[(size_t)BR*KP];
__device__ __nv_bfloat16 g_Wt0h[KP*KP];
__device__ __nv_bfloat16 g_Wt0l[KP*KP];
__device__ __nv_bfloat16 g_Wt1h[KP*KP];
__device__ __nv_bfloat16 g_Wt1l[KP*KP];
__device__ __nv_bfloat16 g_WtIh[HH*KPI];
__device__ __nv_bfloat16 g_WtIl[HH*KPI];

// ---------------------------------------------------------------------------
// f32x2 helpers
// ---------------------------------------------------------------------------
__device__ __forceinline__ unsigned long long pack2(float x, float y) {
    unsigned long long r;
    asm("mov.b64 %0, {%1, %2};" : "=l"(r)
        : "r"(__float_as_uint(x)), "r"(__float_as_uint(y)));
    return r;
}
__device__ __forceinline__ void ffma2(unsigned long long& d, unsigned long long a,
                                      unsigned long long b) {
    asm("fma.rn.f32x2 %0, %1, %2, %3;" : "=l"(d) : "l"(a), "l"(b), "l"(d));
}
__device__ __forceinline__ float2 unpack2(unsigned long long v) {
    unsigned lo, hi;
    asm("mov.b64 {%0, %1}, %2;" : "=r"(lo), "=r"(hi) : "l"(v));
    return make_float2(__uint_as_float(lo), __uint_as_float(hi));
}

#define MMA_BF16(c, a, b0, b1) \
    asm volatile("mma.sync.aligned.m16n8k16.row.col.f32.bf16.bf16.f32 " \
                 "{%0,%1,%2,%3}, {%4,%5,%6,%7}, {%8,%9}, {%0,%1,%2,%3};" \
                 : "+f"((c)[0]), "+f"((c)[1]), "+f"((c)[2]), "+f"((c)[3]) \
                 : "r"((a)[0]), "r"((a)[1]), "r"((a)[2]), "r"((a)[3]), \
                   "r"(b0), "r"(b1))

#define LDSM_X4(R, A) \
    asm volatile("ldmatrix.sync.aligned.m8n8.x4.shared.b16 {%0,%1,%2,%3}, [%4];" \
                 : "=r"((R)[0]), "=r"((R)[1]), "=r"((R)[2]), "=r"((R)[3]) : "r"(A))

__device__ __forceinline__ uint32_t lds_addr(const void* p) {
    return (uint32_t)__cvta_generic_to_shared(p);
}

__device__ __forceinline__ void split_bf16(float v, __nv_bfloat16& h, __nv_bfloat16& l) {
    h = __float2bfloat16(v);
    l = __float2bfloat16(v - __bfloat162float(h));
}

// ---------------------------------------------------------------------------
// Sparse row compaction (adj is binary; ~30% density) + inverse slot map
// ---------------------------------------------------------------------------
__global__ void k_reset() { if (threadIdx.x == 0) g_cnt = 0; }

__global__ void k_compact(const float* __restrict__ adj) {
    int i = blockIdx.x * 256 + threadIdx.x;
    if (i < BR) {
        if (adj[i] != 0.f) {
            int idx = atomicAdd(&g_cnt, 1);
            g_rows[idx] = i;
            g_slot[i] = idx;
        } else {
            g_slot[i] = -1;
        }
    }
}

// ---------------------------------------------------------------------------
// W transpose + split (bond-step weights, KP layout)
// ---------------------------------------------------------------------------
__global__ void k_convW(const float* __restrict__ W,
                        __nv_bfloat16* __restrict__ hi, __nv_bfloat16* __restrict__ lo) {
    int n = blockIdx.x;
    int k = threadIdx.x;
    if (k < HH) {
        float v = W[(size_t)k * HH + n];
        __nv_bfloat16 h, l;
        split_bf16(v, h, l);
        hi[(size_t)n * KP + k] = h;
        lo[(size_t)n * KP + k] = l;
    }
}

// W_i_bond transpose + split (KPI layout, k in [BF,KPI) stays zero-init)
__global__ void k_convWi(const float* __restrict__ W,
                         __nv_bfloat16* __restrict__ hi, __nv_bfloat16* __restrict__ lo) {
    int n = blockIdx.x;          // 0..299
    int k = threadIdx.x;         // 0..159
    if (k < BF) {
        float v = W[(size_t)k * HH + n];
        __nv_bfloat16 h, l;
        split_bf16(v, h, l);
        hi[(size_t)n * KPI + k] = h;
        lo[(size_t)n * KPI + k] = l;
    }
}

// ---------------------------------------------------------------------------
// input_bond via mma.sync: compacted rows only.
// ---------------------------------------------------------------------------
__global__ __launch_bounds__(256)
void k_inbond_mma(const float* __restrict__ A,
                  const __nv_bfloat16* __restrict__ pWh, const __nv_bfloat16* __restrict__ pWl,
                  float* __restrict__ Co,
                  __nv_bfloat16* __restrict__ pH, __nv_bfloat16* __restrict__ pL) {
    extern __shared__ __align__(16) char smraw[];
    __nv_bfloat16 (*sAh)[40] = (__nv_bfloat16(*)[40])(smraw + 0);
    __nv_bfloat16 (*sAl)[40] = (__nv_bfloat16(*)[40])(smraw + 10240);
    __nv_bfloat16 (*sBh)[40] = (__nv_bfloat16(*)[40])(smraw + 20480);
    __nv_bfloat16 (*sBl)[40] = (__nv_bfloat16(*)[40])(smraw + 25600);

    const int cnt = g_cnt;
    const int row0 = blockIdx.y * 128;
    if (row0 >= cnt) return;
    const int col0 = blockIdx.x * 64;
    const int tid = threadIdx.x;
    const int w   = tid >> 5;
    const int rw  = w & 3;
    const int cw  = w >> 2;
    const int lane = tid & 31;
    const int gid = lane >> 2;
    const int q   = lane & 3;

    const int arow  = tid >> 1, ahalf = tid & 1;
    const int bn    = tid >> 2, bpart = tid & 3;
    const int grow  = (row0 + arow < cnt) ? g_rows[row0 + arow] : -1;

    const int aR = rw * 32 + (lane & 15);
    const int aC = (lane >> 4) * 8;
    const uint32_t addrAh = lds_addr(&sAh[aR][aC]);
    const uint32_t addrAl = lds_addr(&sAl[aR][aC]);
    const int bR = cw * 32 + ((lane >> 4) & 1) * 8 + (lane & 7);
    const int bC = ((lane >> 3) & 1) * 8;
    const uint32_t addrBh = lds_addr(&sBh[bR][bC]);
    const uint32_t addrBl = lds_addr(&sBl[bR][bC]);

    float acc[2][4][4];
    #pragma unroll
    for (int mt = 0; mt < 2; mt++)
        #pragma unroll
        for (int nt = 0; nt < 4; nt++)
            #pragma unroll
            for (int e = 0; e < 4; e++) acc[mt][nt][e] = 0.f;

    int k0 = 0;
    for (int it = 0; it < KPI / 32; ++it) {
        __syncthreads();
        {
            int kb = ahalf * 16;
            #pragma unroll
            for (int e = 0; e < 16; e++) {
                int k = k0 + kb + e;
                float v = (grow >= 0 && k < BF) ? A[(size_t)grow * BF + k] : 0.f;
                __nv_bfloat16 vh, vl;
                split_bf16(v, vh, vl);
                sAh[arow][kb + e] = vh;
                sAl[arow][kb + e] = vl;
            }
        }
        {
            const __nv_bfloat16* bBh = pWh + (size_t)(col0 + bn) * KPI + k0 + bpart * 8;
            const __nv_bfloat16* bBl = pWl + (size_t)(col0 + bn) * KPI + k0 + bpart * 8;
            *(uint4*)&sBh[bn][bpart * 8] = *(const uint4*)bBh;
            *(uint4*)&sBl[bn][bpart * 8] = *(const uint4*)bBl;
        }
        __syncthreads();
        #pragma unroll
        for (int ks = 0; ks < 2; ++ks) {
            const uint32_t ko = ks * 32;
            uint32_t afh[2][4], afl[2][4], bfh[2][4], bfl[2][4];
            #pragma unroll
            for (int mt = 0; mt < 2; mt++) {
                LDSM_X4(afh[mt], addrAh + mt * 1280 + ko);
                LDSM_X4(afl[mt], addrAl + mt * 1280 + ko);
            }
            #pragma unroll
            for (int p = 0; p < 2; p++) {
                LDSM_X4(bfh[p], addrBh + p * 1280 + ko);
                LDSM_X4(bfl[p], addrBl + p * 1280 + ko);
            }
            #pragma unroll
            for (int p = 0; p < 2; p++)
                #pragma unroll
                for (int s = 0; s < 2; s++) {
                    const int nt = 2 * p + s;
                    #pragma unroll
                    for (int mt = 0; mt < 2; mt++) {
                        MMA_BF16(acc[mt][nt], afh[mt], bfh[p][2 * s], bfh[p][2 * s + 1]);
                        MMA_BF16(acc[mt][nt], afh[mt], bfl[p][2 * s], bfl[p][2 * s + 1]);
                        MMA_BF16(acc[mt][nt], afl[mt], bfh[p][2 * s], bfh[p][2 * s + 1]);
                    }
                }
        }
        k0 += 32;
    }

    #pragma unroll
    for (int mt = 0; mt < 2; mt++) {
        #pragma unroll
        for (int rp = 0; rp < 2; rp++) {
            int lr = rw * 32 + mt * 16 + gid + rp * 8;
            int slot = row0 + lr;
            if (slot < cnt) {
                size_t row = g_rows[slot];
                #pragma unroll
                for (int nt = 0; nt < 4; nt++) {
                    int c = cw * 32 + nt * 8 + q * 2;
                    int h = col0 + c;
                    if (h < HH) {
                        float v0 = fmaxf(acc[mt][nt][rp * 2 + 0], 0.f);
                        float v1 = fmaxf(acc[mt][nt][rp * 2 + 1], 0.f);
                        *(float2*)&Co[row * HH + h] = make_float2(v0, v1);
                        __nv_bfloat16 h0, l0, h1, l1;
                        split_bf16(v0, h0, l0);
                        split_bf16(v1, h1, l1);
                        __nv_bfloat162 hp; hp.x = h0; hp.y = h1;
                        __nv_bfloat162 lp; lp.x = l0; lp.y = l1;
                        *(__nv_bfloat162*)&pH[row * KP + h] = hp;
                        *(__nv_bfloat162*)&pL[row * KP + h] = lp;
                    }
                }
            }
        }
    }
}

// ---------------------------------------------------------------------------
// f32x2 SGEMM (maW only): C = A @ W
// ---------------------------------------------------------------------------
#define BKg 12
template<int K>
__global__ __launch_bounds__(128, 3)
void k_gemm_f2(const float* __restrict__ A, const float* __restrict__ W,
               float* __restrict__ Co, int N) {
    const int row0 = blockIdx.y * 128;
    const int col0 = blockIdx.x * 64;
    __shared__ __align__(16) float As[BKg][132];
    __shared__ __align__(16) float Bs[BKg][72];
    const int tid = threadIdx.x;
    const int rg = tid >> 3;
    const int cg = tid & 7;

    int ar[3], ac4[3];
    #pragma unroll
    for (int q = 0; q < 3; q++) {
        int l = q * 128 + tid;
        ar[q]  = l / 3;
        ac4[q] = l - ar[q] * 3;
    }
    const int bk0  = tid >> 4;
    const int bk1  = (tid + 128) >> 4;
    const int bc4  = tid & 15;
    const bool hasB1  = (tid < 64);
    const bool bcolOK = (col0 + 4 * bc4 + 4 <= N);

    unsigned long long acc[8][4];
    #pragma unroll
    for (int i = 0; i < 8; i++)
        #pragma unroll
        for (int p = 0; p < 4; p++) acc[i][p] = 0ull;

    float4 ra[3], rb0, rb1;
    auto load_tile = [&](int k0) {
        #pragma unroll
        for (int q = 0; q < 3; q++)
            ra[q] = *(const float4*)&A[(size_t)(row0 + ar[q]) * K + k0 + 4 * ac4[q]];
        {
            int gk = k0 + bk0;
            rb0 = (gk < K && bcolOK) ? *(const float4*)&W[(size_t)gk * N + col0 + 4 * bc4]
                                     : make_float4(0.f, 0.f, 0.f, 0.f);
        }
        if (hasB1) {
            int gk = k0 + bk1;
            rb1 = (gk < K && bcolOK) ? *(const float4*)&W[(size_t)gk * N + col0 + 4 * bc4]
                                     : make_float4(0.f, 0.f, 0.f, 0.f);
        }
    };

    const int nIter = (K + BKg - 1) / BKg;
    load_tile(0);
    int k0 = 0;
    for (int it = 0; it < nIter; ++it) {
        __syncthreads();
        #pragma unroll
        for (int q = 0; q < 3; q++) {
            int kb = 4 * ac4[q];
            As[kb + 0][ar[q]] = ra[q].x;
            As[kb + 1][ar[q]] = ra[q].y;
            As[kb + 2][ar[q]] = ra[q].z;
            As[kb + 3][ar[q]] = ra[q].w;
        }
        *(float4*)&Bs[bk0][4 * bc4] = rb0;
        if (hasB1) *(float4*)&Bs[bk1][4 * bc4] = rb1;
        __syncthreads();
        if (it + 1 < nIter) load_tile(k0 + BKg);
        #pragma unroll
        for (int kk = 0; kk < BKg; ++kk) {
            float4 a0 = *(const float4*)&As[kk][rg * 8];
            float4 a1 = *(const float4*)&As[kk][rg * 8 + 4];
            ulonglong2 b01 = *(const ulonglong2*)&Bs[kk][cg * 8];
            ulonglong2 b23 = *(const ulonglong2*)&Bs[kk][cg * 8 + 4];
            float av[8] = {a0.x, a0.y, a0.z, a0.w, a1.x, a1.y, a1.z, a1.w};
            #pragma unroll
            for (int i = 0; i < 8; i++) {
                unsigned long long ap = pack2(av[i], av[i]);
                ffma2(acc[i][0], ap, b01.x);
                ffma2(acc[i][1], ap, b01.y);
                ffma2(acc[i][2], ap, b23.x);
                ffma2(acc[i][3], ap, b23.y);
            }
        }
        k0 += BKg;
    }

    const bool fastcol = (col0 + 64 <= N);
    #pragma unroll
    for (int i = 0; i < 8; i++) {
        size_t row = row0 + rg * 8 + i;
        float v[8];
        #pragma unroll
        for (int p = 0; p < 4; p++) {
            float2 f = unpack2(acc[i][p]);
            v[2 * p] = f.x; v[2 * p + 1] = f.y;
        }
        size_t base = row * N + col0 + cg * 8;
        if (fastcol) {
            *(float4*)&Co[base]     = make_float4(v[0], v[1], v[2], v[3]);
            *(float4*)&Co[base + 4] = make_float4(v[4], v[5], v[6], v[7]);
        } else {
            #pragma unroll
            for (int jj = 0; jj < 8; jj++)
                if (col0 + cg * 8 + jj < N) Co[base + jj] = v[jj];
        }
    }
}

// ---------------------------------------------------------------------------
// Compacted-row mma.sync GEMM (step 0): Cc[slot,:] = prev@W
// Round-16: last mainloop iteration runs ks=0 only (cols [304,320) are zero).
// ---------------------------------------------------------------------------
__global__ __launch_bounds__(256)
void k_gemmc_mma(const __nv_bfloat16* __restrict__ pAh, const __nv_bfloat16* __restrict__ pAl,
                 const __nv_bfloat16* __restrict__ pWh, const __nv_bfloat16* __restrict__ pWl,
                 float* __restrict__ Cc) {
    extern __shared__ __align__(16) char smraw[];
    __nv_bfloat16 (*sAh)[40] = (__nv_bfloat16(*)[40])(smraw + 0);
    __nv_bfloat16 (*sAl)[40] = (__nv_bfloat16(*)[40])(smraw + 10240);
    __nv_bfloat16 (*sBh)[40] = (__nv_bfloat16(*)[40])(smraw + 20480);
    __nv_bfloat16 (*sBl)[40] = (__nv_bfloat16(*)[40])(smraw + 25600);

    const int cnt = g_cnt;
    const int row0 = blockIdx.y * 128;
    if (row0 >= cnt) return;
    const int col0 = blockIdx.x * 64;
    const int tid = threadIdx.x;
    const int w   = tid >> 5;
    const int rw  = w & 3;
    const int cw  = w >> 2;
    const int lane = tid & 31;
    const int gid = lane >> 2;
    const int q   = lane & 3;

    const int arow  = tid >> 1, apart = tid & 1;
    const int bn    = tid >> 2, bpart = tid & 3;
    const int grow  = (row0 + arow < cnt) ? g_rows[row0 + arow] : -1;

    const int aR = rw * 32 + (lane & 15);
    const int aC = (lane >> 4) * 8;
    const uint32_t addrAh = lds_addr(&sAh[aR][aC]);
    const uint32_t addrAl = lds_addr(&sAl[aR][aC]);
    const int bR = cw * 32 + ((lane >> 4) & 1) * 8 + (lane & 7);
    const int bC = ((lane >> 3) & 1) * 8;
    const uint32_t addrBh = lds_addr(&sBh[bR][bC]);
    const uint32_t addrBl = lds_addr(&sBl[bR][bC]);

    float acc[2][4][4];
    #pragma unroll
    for (int mt = 0; mt < 2; mt++)
        #pragma unroll
        for (int nt = 0; nt < 4; nt++)
            #pragma unroll
            for (int e = 0; e < 4; e++) acc[mt][nt][e] = 0.f;

    uint4 rAh[2], rAl[2], rBh, rBl;
    auto load_tile = [&](int k0) {
        if (grow >= 0) {
            const __nv_bfloat16* bAh = pAh + (size_t)grow * KP + k0 + apart * 16;
            const __nv_bfloat16* bAl = pAl + (size_t)grow * KP + k0 + apart * 16;
            rAh[0] = *(const uint4*)bAh;  rAh[1] = *(const uint4*)(bAh + 8);
            rAl[0] = *(const uint4*)bAl;  rAl[1] = *(const uint4*)(bAl + 8);
        } else {
            rAh[0] = rAh[1] = rAl[0] = rAl[1] = make_uint4(0, 0, 0, 0);
        }
        const __nv_bfloat16* bBh = pWh + (size_t)(col0 + bn) * KP + k0 + bpart * 8;
        const __nv_bfloat16* bBl = pWl + (size_t)(col0 + bn) * KP + k0 + bpart * 8;
        rBh = *(const uint4*)bBh;
        rBl = *(const uint4*)bBl;
    };

    load_tile(0);
    int k0 = 0;
    for (int it = 0; it < NIT_KP; ++it) {
        __syncthreads();
        *(uint4*)&sAh[arow][apart * 16]     = rAh[0];
        *(uint4*)&sAh[arow][apart * 16 + 8] = rAh[1];
        *(uint4*)&sAl[arow][apart * 16]     = rAl[0];
        *(uint4*)&sAl[arow][apart * 16 + 8] = rAl[1];
        *(uint4*)&sBh[bn][bpart * 8] = rBh;
        *(uint4*)&sBl[bn][bpart * 8] = rBl;
        __syncthreads();
        if (it + 1 < NIT_KP) load_tile(k0 + 32);
        const int nks = (it == NIT_KP - 1) ? 1 : 2;   // tail: cols 304-319 are zero
        for (int ks = 0; ks < nks; ++ks) {
            const uint32_t ko = ks * 32;
            uint32_t afh[2][4], afl[2][4], bfh[2][4], bfl[2][4];
            #pragma unroll
            for (int mt = 0; mt < 2; mt++) {
                LDSM_X4(afh[mt], addrAh + mt * 1280 + ko);
                LDSM_X4(afl[mt], addrAl + mt * 1280 + ko);
            }
            #pragma unroll
            for (int p = 0; p < 2; p++) {
                LDSM_X4(bfh[p], addrBh + p * 1280 + ko);
                LDSM_X4(bfl[p], addrBl + p * 1280 + ko);
            }
            #pragma unroll
            for (int p = 0; p < 2; p++)
                #pragma unroll
                for (int s = 0; s < 2; s++) {
                    const int nt = 2 * p + s;
                    #pragma unroll
                    for (int mt = 0; mt < 2; mt++) {
                        MMA_BF16(acc[mt][nt], afh[mt], bfh[p][2 * s], bfh[p][2 * s + 1]);
                        MMA_BF16(acc[mt][nt], afh[mt], bfl[p][2 * s], bfl[p][2 * s + 1]);
                        MMA_BF16(acc[mt][nt], afl[mt], bfh[p][2 * s], bfh[p][2 * s + 1]);
                    }
                }
        }
        k0 += 32;
    }

    #pragma unroll
    for (int mt = 0; mt < 2; mt++) {
        #pragma unroll
        for (int rp = 0; rp < 2; rp++) {
            int lr = rw * 32 + mt * 16 + gid + rp * 8;
            int slot = row0 + lr;
            if (slot < cnt) {
                #pragma unroll
                for (int nt = 0; nt < 4; nt++) {
                    int c = cw * 32 + nt * 8 + q * 2;
                    int h = col0 + c;
                    if (h < HH) {
                        *(float2*)&Cc[(size_t)slot * HH + h] =
                            make_float2(acc[mt][nt][rp * 2 + 0], acc[mt][nt][rp * 2 + 1]);
                    }
                }
            }
        }
    }
}

// ---------------------------------------------------------------------------
// Step-0 epilogue, 160 threads, one float2 column per thread (round-16).
// ---------------------------------------------------------------------------
__global__ void k_epilogue0(const float* __restrict__ ib, const float* __restrict__ maW,
                            const float* __restrict__ Cc, const float* __restrict__ adj,
                            __nv_bfloat16* __restrict__ pOh, __nv_bfloat16* __restrict__ pOl) {
    int gj = blockIdx.x;
    int g = gj >> 6, j = gj & 63;
    __shared__ float adjT[64], smv[64];
    __shared__ int   slots[64];
    int tid = threadIdx.x;        // 160
    if (tid < 64) {
        adjT[tid]  = adj[((size_t)(g * 64 + j)) * 64 + tid];
        smv[tid]   = g_sm[((size_t)(g * 64 + tid)) * 64 + j];
        slots[tid] = g_slot[((size_t)(g * 64 + j)) * 64 + tid];
    }
    __syncthreads();
    const int h0 = 2 * tid;
    if (h0 >= HH) return;
    float2 s0 = make_float2(0.f, 0.f);
    float2 m0 = make_float2(-INFINITY, -INFINITY);
    for (int i = 0; i < 64; ++i) {
        size_t rowOut = ((size_t)(g * 64 + i) * 64 + j);
        size_t obase  = rowOut * HH;
        size_t pbase  = rowOut * KP;
        size_t rowM   = (size_t)(g * 64 + i) * HH;
        int slot = slots[i];
        float a = adjT[i], wv = smv[i];
        float2 ibv = *(const float2*)&ib[obase + h0];
        float2 mw  = *(const float2*)&maW[rowM + h0];
        float2 cv  = (slot >= 0) ? *(const float2*)&Cc[(size_t)slot * HH + h0]
                                 : make_float2(0.f, 0.f);
        float v0 = fmaxf(ibv.x + a * mw.x - cv.x, 0.f) * wv;
        float v1 = fmaxf(ibv.y + a * mw.y - cv.y, 0.f) * wv;
        __nv_bfloat16 vh0, vl0, vh1, vl1;
        split_bf16(v0, vh0, vl0);
        split_bf16(v1, vh1, vl1);
        __nv_bfloat162 hp; hp.x = vh0; hp.y = vh1;
        __nv_bfloat162 lp; lp.x = vl0; lp.y = vl1;
        *(__nv_bfloat162*)&pOh[pbase + h0] = hp;
        *(__nv_bfloat162*)&pOl[pbase + h0] = lp;
        s0.x += v0;  s0.y += v1;
        m0.x = fmaxf(m0.x, v0);  m0.y = fmaxf(m0.y, v1);
    }
    {
        size_t base = (size_t)(g * 64 + j) * HH;
        float2 cur = *(float2*)&g_msg_atom[base + h0];
        cur.x += s0.x * (1.f / (1.f + expf(-m0.x)));
        cur.y += s0.y * (1.f / (1.f + expf(-m0.y)));
        *(float2*)&g_msg_atom[base + h0] = cur;
    }
}

// ---------------------------------------------------------------------------
// Tensor-core fused bond step (step 1). Round-16: ks=0-only tail iteration.
// ---------------------------------------------------------------------------
template<int UPDATE, int EMIT, int STORE>
__global__ __launch_bounds__(256)
void k_bondstep_mma(const __nv_bfloat16* __restrict__ pAh, const __nv_bfloat16* __restrict__ pAl,
                    const __nv_bfloat16* __restrict__ pWh, const __nv_bfloat16* __restrict__ pWl,
                    const float* __restrict__ ib, const float* __restrict__ maW,
                    const float* __restrict__ adj, float* __restrict__ mbout,
                    __nv_bfloat16* __restrict__ pOh, __nv_bfloat16* __restrict__ pOl) {
    extern __shared__ __align__(16) char smraw[];
    __nv_bfloat16 (*sAh)[40] = (__nv_bfloat16(*)[40])(smraw + 0);
    __nv_bfloat16 (*sAl)[40] = (__nv_bfloat16(*)[40])(smraw + 10240);
    __nv_bfloat16 (*sBh)[40] = (__nv_bfloat16(*)[40])(smraw + 20480);
    __nv_bfloat16 (*sBl)[40] = (__nv_bfloat16(*)[40])(smraw + 25600);
    float (*maWs)[68]        = (float(*)[68])(smraw + 30720);
    float (*psum)[65]        = (float(*)[65])(smraw + 48128);
    float (*pmax)[65]        = (float(*)[65])(smraw + 56448);
    float (*adjs)[64]        = (float(*)[64])(smraw + 64768);
    float (*smvv)[64]        = (float(*)[64])(smraw + 65280);

    const int row0 = blockIdx.y * 128;
    const int col0 = blockIdx.x * 64;
    const int g  = row0 >> 12;
    const int x0 = (row0 >> 6) & 63;
    const int tid = threadIdx.x;
    const int w   = tid >> 5;
    const int rw  = w & 3;
    const int cw  = w >> 2;
    const int lane = tid & 31;
    const int gid = lane >> 2;
    const int q   = lane & 3;

    if (tid < 128) {
        int xl = tid >> 6, y = tid & 63;
        adjs[xl][y] = adj[(size_t)(g * 64 + x0 + xl) * 64 + y];
        smvv[xl][y] = g_sm[(size_t)(g * 64 + y) * 64 + x0 + xl];
    }
    for (int l = tid; l < 64 * 16; l += 256) {
        int y = l >> 4, c4 = (l & 15) * 4;
        int c = col0 + c4;
        float4 v;
        if (c + 4 <= HH) v = *(const float4*)&maW[(size_t)(g * 64 + y) * HH + c];
        else {
            float t[4];
            #pragma unroll
            for (int e = 0; e < 4; e++)
                t[e] = (c + e < HH) ? maW[(size_t)(g * 64 + y) * HH + c + e] : 0.f;
            v = make_float4(t[0], t[1], t[2], t[3]);
        }
        *(float4*)&maWs[y][c4] = v;
    }

    const int arow  = tid >> 1, apart = tid & 1;
    const int bn    = tid >> 2, bpart = tid & 3;

    const int aR = rw * 32 + (lane & 15);
    const int aC = (lane >> 4) * 8;
    const uint32_t addrAh = lds_addr(&sAh[aR][aC]);
    const uint32_t addrAl = lds_addr(&sAl[aR][aC]);
    const int bR = cw * 32 + ((lane >> 4) & 1) * 8 + (lane & 7);
    const int bC = ((lane >> 3) & 1) * 8;
    const uint32_t addrBh = lds_addr(&sBh[bR][bC]);
    const uint32_t addrBl = lds_addr(&sBl[bR][bC]);

    float acc[2][4][4];
    #pragma unroll
    for (int mt = 0; mt < 2; mt++)
        #pragma unroll
        for (int nt = 0; nt < 4; nt++)
            #pragma unroll
            for (int e = 0; e < 4; e++) acc[mt][nt][e] = 0.f;

    uint4 rAh[2], rAl[2], rBh, rBl;
    auto load_tile = [&](int k0) {
        const __nv_bfloat16* bAh = pAh + (size_t)(row0 + arow) * KP + k0 + apart * 16;
        const __nv_bfloat16* bAl = pAl + (size_t)(row0 + arow) * KP + k0 + apart * 16;
        rAh[0] = *(const uint4*)bAh;  rAh[1] = *(const uint4*)(bAh + 8);
        rAl[0] = *(const uint4*)bAl;  rAl[1] = *(const uint4*)(bAl + 8);
        const __nv_bfloat16* bBh = pWh + (size_t)(col0 + bn) * KP + k0 + bpart * 8;
        const __nv_bfloat16* bBl = pWl + (size_t)(col0 + bn) * KP + k0 + bpart * 8;
        rBh = *(const uint4*)bBh;
        rBl = *(const uint4*)bBl;
    };

    load_tile(0);
    int k0 = 0;
    for (int it = 0; it < NIT_KP; ++it) {
        __syncthreads();
        *(uint4*)&sAh[arow][apart * 16]     = rAh[0];
        *(uint4*)&sAh[arow][apart * 16 + 8] = rAh[1];
        *(uint4*)&sAl[arow][apart * 16]     = rAl[0];
        *(uint4*)&sAl[arow][apart * 16 + 8] = rAl[1];
        *(uint4*)&sBh[bn][bpart * 8] = rBh;
        *(uint4*)&sBl[bn][bpart * 8] = rBl;
        __syncthreads();
        if (it + 1 < NIT_KP) load_tile(k0 + 32);
        const int nks = (it == NIT_KP - 1) ? 1 : 2;   // tail: cols 304-319 are zero
        for (int ks = 0; ks < nks; ++ks) {
            const uint32_t ko = ks * 32;
            uint32_t afh[2][4], afl[2][4], bfh[2][4], bfl[2][4];
            #pragma unroll
            for (int mt = 0; mt < 2; mt++) {
                LDSM_X4(afh[mt], addrAh + mt * 1280 + ko);
                LDSM_X4(afl[mt], addrAl + mt * 1280 + ko);
            }
            #pragma unroll
            for (int p = 0; p < 2; p++) {
                LDSM_X4(bfh[p], addrBh + p * 1280 + ko);
                LDSM_X4(bfl[p], addrBl + p * 1280 + ko);
            }
            #pragma unroll
            for (int p = 0; p < 2; p++)
                #pragma unroll
                for (int s = 0; s < 2; s++) {
                    const int nt = 2 * p + s;
                    #pragma unroll
                    for (int mt = 0; mt < 2; mt++) {
                        MMA_BF16(acc[mt][nt], afh[mt], bfh[p][2 * s], bfh[p][2 * s + 1]);
                        MMA_BF16(acc[mt][nt], afh[mt], bfl[p][2 * s], bfl[p][2 * s + 1]);
                        MMA_BF16(acc[mt][nt], afl[mt], bfh[p][2 * s], bfh[p][2 * s + 1]);
                    }
                }
        }
        k0 += 32;
    }

    float tsum[4][2], tmax[4][2];
    #pragma unroll
    for (int nt = 0; nt < 4; nt++)
        #pragma unroll
        for (int p = 0; p < 2; p++) { tsum[nt][p] = 0.f; tmax[nt][p] = -INFINITY; }

    #pragma unroll
    for (int mt = 0; mt < 2; mt++) {
        #pragma unroll
        for (int rp = 0; rp < 2; rp++) {
            int lr = rw * 32 + mt * 16 + gid + rp * 8;
            int xl = lr >> 6, y = lr & 63;
            int x  = x0 + xl;
            float a = adjs[xl][y];
            float wv = smvv[xl][y];
            size_t brow = (size_t)(g * 64 + y) * 64 + x;
            #pragma unroll
            for (int nt = 0; nt < 4; nt++) {
                int c = cw * 32 + nt * 8 + q * 2;
                int h = col0 + c;
                if (h < HH) {
                    size_t ob = brow * HH + h;
                    float2 ibv = *(const float2*)&ib[ob];
                    float v0 = fmaxf(ibv.x + a * maWs[y][c]     - acc[mt][nt][rp * 2 + 0], 0.f) * wv;
                    float v1 = fmaxf(ibv.y + a * maWs[y][c + 1] - acc[mt][nt][rp * 2 + 1], 0.f) * wv;
                    if (STORE) *(float2*)&mbout[ob] = make_float2(v0, v1);
                    if (EMIT) {
                        __nv_bfloat16 h0, l0, h1, l1;
                        split_bf16(v0, h0, l0);
                        split_bf16(v1, h1, l1);
                        size_t pb = brow * KP + h;
                        __nv_bfloat162 hp; hp.x = h0; hp.y = h1;
                        __nv_bfloat162 lp; lp.x = l0; lp.y = l1;
                        *(__nv_bfloat162*)&pOh[pb] = hp;
                        *(__nv_bfloat162*)&pOl[pb] = lp;
                    }
                    tsum[nt][0] += v0;  tmax[nt][0] = fmaxf(tmax[nt][0], v0);
                    tsum[nt][1] += v1;  tmax[nt][1] = fmaxf(tmax[nt][1], v1);
                }
            }
        }
    }
    {
        int slot = rw * 8 + gid;
        #pragma unroll
        for (int nt = 0; nt < 4; nt++) {
            int c = cw * 32 + nt * 8 + q * 2;
            psum[slot][c]     = tsum[nt][0];
            psum[slot][c + 1] = tsum[nt][1];
            pmax[slot][c]     = tmax[nt][0];
            pmax[slot][c + 1] = tmax[nt][1];
        }
    }
    __syncthreads();
    if (tid < 128) {
        int xl = tid >> 6, c = tid & 63;
        if (col0 + c < HH) {
            float s = 0.f, m = -INFINITY;
            #pragma unroll
            for (int r = 0; r < 16; r++) {
                s += psum[xl * 16 + r][c];
                m = fmaxf(m, pmax[xl * 16 + r][c]);
            }
            float aggv = s * (1.f / (1.f + expf(-m)));
            size_t idx = (size_t)(g * 64 + x0 + xl) * HH + col0 + c;
            if (UPDATE) g_msg_atom[idx] += aggv;
            else        g_agg[idx] = aggv;
        }
    }
}

// ---------------------------------------------------------------------------
// input_atom = relu(f_atoms @ W_i_atom) (also -> msg_atom)
// ---------------------------------------------------------------------------
__global__ void k_input_atom(const float* __restrict__ A, const float* __restrict__ W) {
    const int row0 = blockIdx.y * 64;
    const int col0 = blockIdx.x * 64;
    __shared__ float As[16][68];
    __shared__ float Bs[16][68];
    const int tid = threadIdx.x;
    const int tx = tid & 15, ty = tid >> 4;
    float acc[4][4] = {};
    for (int k0 = 0; k0 < AF; k0 += 16) {
        __syncthreads();
        {
            int kk = tid & 15;
            int k  = k0 + kk;
            #pragma unroll
            for (int qq = 0; qq < 4; qq++) {
                int r = (tid >> 4) + qq * 16;
                As[kk][r] = (k < AF) ? A[(row0 + r) * AF + k] : 0.f;
            }
        }
        {
            int nn = tid & 63;
            int c  = col0 + nn;
            #pragma unroll
            for (int qq = 0; qq < 4; qq++) {
                int kk = (tid >> 6) + qq * 4;
                int k  = k0 + kk;
                Bs[kk][nn] = (k < AF && c < HH) ? W[k * HH + c] : 0.f;
            }
        }
        __syncthreads();
        #pragma unroll
        for (int kk = 0; kk < 16; kk++) {
            float4 a4 = *(const float4*)&As[kk][ty * 4];
            float4 b4 = *(const float4*)&Bs[kk][tx * 4];
            float a[4] = {a4.x, a4.y, a4.z, a4.w};
            float b[4] = {b4.x, b4.y, b4.z, b4.w};
            #pragma unroll
            for (int i = 0; i < 4; i++)
                #pragma unroll
                for (int j = 0; j < 4; j++)
                    acc[i][j] += a[i] * b[j];
        }
    }
    #pragma unroll
    for (int i = 0; i < 4; i++) {
        int r = row0 + ty * 4 + i;
        #pragma unroll
        for (int j = 0; j < 4; j++) {
            int c = col0 + tx * 4 + j;
            if (c < HH) {
                float v = acc[i][j];
                v = v > 0.f ? v : 0.f;
                g_input_atom[r * HH + c] = v;
                g_msg_atom[r * HH + c]   = v;
            }
        }
    }
}

// ---------------------------------------------------------------------------
// agg over input_bond with adjacency skip — float2-vectorized.
// ---------------------------------------------------------------------------
__global__ void k_agg(const float* __restrict__ mb, const float* __restrict__ adj) {
    int gm = blockIdx.x;
    int g = gm >> 6, m = gm & 63;
    __shared__ float adjc[64];
    int tid = threadIdx.x;       // 160
    if (tid < 64) adjc[tid] = adj[(size_t)(g * 64 + tid) * 64 + m];
    __syncthreads();
    int h = 2 * tid;
    if (h >= HH) return;
    const float* base = mb + ((size_t)(g * 64) * 64 + m) * HH + h;
    float2 s = make_float2(0.f, 0.f);
    float2 mx = make_float2(0.f, 0.f);
    for (int n = 0; n < 64; n++) {
        if (adjc[n] != 0.f) {
            float2 v = *(const float2*)&base[(size_t)n * 64 * HH];
            s.x += v.x;  s.y += v.y;
            mx.x = fmaxf(mx.x, v.x);  mx.y = fmaxf(mx.y, v.y);
        }
    }
    size_t idx = (size_t)gm * HH + h;
    float2 cur = *(float2*)&g_msg_atom[idx];
    cur.x += s.x * (1.f / (1.f + expf(-mx.x)));
    cur.y += s.y * (1.f / (1.f + expf(-mx.y)));
    *(float2*)&g_msg_atom[idx] = cur;
}

// ---------------------------------------------------------------------------
// Resonance + softmax, 4 column-tiles per graph (128 blocks).
// ---------------------------------------------------------------------------
__global__ void k_resonance4(const float* __restrict__ adj) {
    int g  = blockIdx.x >> 2;
    int qt = blockIdx.x & 3;
    __shared__ float mt[64][101];
    __shared__ float rr[64][17];
    int tid = threadIdx.x;
    int tx = tid & 15;
    int ty = tid >> 4;
    float acc[4] = {};
    for (int c = 0; c < 3; ++c) {
        __syncthreads();
        for (int l = tid; l < 6400; l += 256) {
            int r = l / 100, k = l - r * 100;
            mt[r][k] = g_msg_atom[((size_t)(g * 64 + r)) * 300 + c * 100 + k];
        }
        __syncthreads();
        for (int kk = 0; kk < 100; ++kk) {
            float b = mt[qt * 16 + tx][kk];
            #pragma unroll
            for (int i = 0; i < 4; i++)
                acc[i] += mt[ty * 4 + i][kk] * b;
        }
    }
    #pragma unroll
    for (int i = 0; i < 4; i++)
        rr[ty * 4 + i][tx] = acc[i];
    __syncthreads();
    if (tid < 16) {
        int m = qt * 16 + tid;
        float mxv = -INFINITY;
        for (int n = 0; n < 64; n++) {
            float v = rr[n][tid] * adj[((size_t)(g * 64 + n)) * 64 + m];
            rr[n][tid] = v;
            mxv = fmaxf(mxv, v);
        }
        float sum = 0.f;
        for (int n = 0; n < 64; n++) {
            float e = expf(rr[n][tid] - mxv);
            rr[n][tid] = e;
            sum += e;
        }
        float inv = 1.f / sum;
        for (int n = 0; n < 64; n++)
            g_sm[(size_t)(g * 64 + n) * 64 + m] = rr[n][tid] * inv;
    }
}

// ---------------------------------------------------------------------------
__global__ void k_output(const float* __restrict__ W, const float* __restrict__ bias,
                         float* __restrict__ out) {
    const int row0 = blockIdx.y * 64;
    const int col0 = blockIdx.x * 64;
    __shared__ float As[16][68];
    __shared__ float Bs[16][68];
    const int tid = threadIdx.x;
    const int tx = tid & 15, ty = tid >> 4;
    float acc[4][4] = {};
    for (int k0 = 0; k0 < 900; k0 += 16) {
        __syncthreads();
        {
            int kk = tid & 15;
            int k  = k0 + kk;
            #pragma unroll
            for (int qq = 0; qq < 4; qq++) {
                int r = (tid >> 4) + qq * 16;
                int row = row0 + r;
                float v = 0.f;
                if (k < 900) {
                    if (k < 300)       v = g_agg[row * HH + k];
                    else if (k < 600)  v = g_msg_atom[row * HH + (k - 300)];
                    else               v = g_input_atom[row * HH + (k - 600)];
                }
                As[kk][r] = v;
            }
        }
        {
            int nn = tid & 63;
            int c  = col0 + nn;
            #pragma unroll
            for (int qq = 0; qq < 4; qq++) {
                int kk = (tid >> 6) + qq * 4;
                int k  = k0 + kk;
                Bs[kk][nn] = (k < 900 && c < HH) ? W[k * HH + c] : 0.f;
            }
        }
        __syncthreads();
        #pragma unroll
        for (int kk = 0; kk < 16; kk++) {
            float4 a4 = *(const float4*)&As[kk][ty * 4];
            float4 b4 = *(const float4*)&Bs[kk][tx * 4];
            float a[4] = {a4.x, a4.y, a4.z, a4.w};
            float b[4] = {b4.x, b4.y, b4.z, b4.w};
            #pragma unroll
            for (int i = 0; i < 4; i++)
                #pragma unroll
                for (int j = 0; j < 4; j++)
                    acc[i][j] += a[i] * b[j];
        }
    }
    #pragma unroll
    for (int i = 0; i < 4; i++) {
        int r = row0 + ty * 4 + i;
        #pragma unroll
        for (int j = 0; j < 4; j++) {
            int c = col0 + tx * 4 + j;
            if (c < HH) {
                float v = acc[i][j] + bias[c];
                out[r * HH + c] = v > 0.f ? v : 0.f;
            }
        }
    }
}

// ---------------------------------------------------------------------------
extern "C" void kernel_launch(void* const* d_in, const int* in_sizes, int n_in,
                              void* d_out, int out_size) {
    const float* f_atoms  = (const float*)d_in[0];
    const float* f_bonds  = (const float*)d_in[1];
    const float* adj      = (const float*)d_in[2];
    const float* W_i_atom = (const float*)d_in[3];
    const float* W_i_bond = (const float*)d_in[4];
    const float* W_h0     = (const float*)d_in[5];
    const float* W_h1     = (const float*)d_in[6];
    const float* W_o      = (const float*)d_in[7];
    const float* b_o      = (const float*)d_in[8];
    float* out = (float*)d_out;

    float *p_inbond = 0, *p_mbB = 0, *p_msg = 0, *p_maW = 0, *p_Cc = 0;
    __nv_bfloat16 *p0h = 0, *p0l = 0, *p1h = 0, *p1l = 0;
    __nv_bfloat16 *wt0h = 0, *wt0l = 0, *wt1h = 0, *wt1l = 0, *wtih = 0, *wtil = 0;
    cudaGetSymbolAddress((void**)&p_inbond, g_input_bond);
    cudaGetSymbolAddress((void**)&p_mbB, g_mbB);
    cudaGetSymbolAddress((void**)&p_msg, g_msg_atom);
    cudaGetSymbolAddress((void**)&p_maW, g_maW);
    cudaGetSymbolAddress((void**)&p_Cc, g_Cc);
    cudaGetSymbolAddress((void**)&p0h, g_P0h);
    cudaGetSymbolAddress((void**)&p0l, g_P0l);
    cudaGetSymbolAddress((void**)&p1h, g_P1h);
    cudaGetSymbolAddress((void**)&p1l, g_P1l);
    cudaGetSymbolAddress((void**)&wt0h, g_Wt0h);
    cudaGetSymbolAddress((void**)&wt0l, g_Wt0l);
    cudaGetSymbolAddress((void**)&wt1h, g_Wt1h);
    cudaGetSymbolAddress((void**)&wt1l, g_Wt1l);
    cudaGetSymbolAddress((void**)&wtih, g_WtIh);
    cudaGetSymbolAddress((void**)&wtil, g_WtIl);

    float* mb_final = (out_size >= AR * HH + BR * HH) ? (out + AR * HH) : p_mbB;

    const int SMEM_MMA = 66560;
    const int SMEM_GC  = 30720;
    cudaFuncSetAttribute(k_bondstep_mma<0, 0, 1>,
                         cudaFuncAttributeMaxDynamicSharedMemorySize, SMEM_MMA);
    cudaFuncSetAttribute(k_gemmc_mma,
                         cudaFuncAttributeMaxDynamicSharedMemorySize, SMEM_GC);
    cudaFuncSetAttribute(k_inbond_mma,
                         cudaFuncAttributeMaxDynamicSharedMemorySize, SMEM_GC);

    // sparsity compaction (adj binary, ~30% dense) + slot map
    k_reset<<<1, 32>>>();
    k_compact<<<(BR + 255) / 256, 256>>>(adj);

    k_input_atom<<<dim3(5, 32), 256>>>(f_atoms, W_i_atom);
    k_convW<<<HH, KP>>>(W_h0, wt0h, wt0l);
    k_convW<<<HH, KP>>>(W_h1, wt1h, wt1l);
    k_convWi<<<HH, KPI>>>(W_i_bond, wtih, wtil);
    // input_bond over nonzero rows only via tensor cores (fp32 ib + P0 planes)
    k_inbond_mma<<<dim3(5, BR / 128), 256, SMEM_GC>>>(f_bonds, wtih, wtil,
                                                      p_inbond, p0h, p0l);

    // ---- depth step 0 (prev = input_bond, 70% zero rows -> compacted GEMM) ----
    k_agg<<<2048, 160>>>(p_inbond, adj);
    k_resonance4<<<128, 256>>>(adj);
    k_gemm_f2<HH><<<dim3(5, AR / 128), 128>>>(p_msg, W_h0, p_maW, HH);
    k_gemmc_mma<<<dim3(5, BR / 128), 256, SMEM_GC>>>(p0h, p0l, wt0h, wt0l, p_Cc);
    k_epilogue0<<<2048, 160>>>(p_inbond, p_maW, p_Cc, adj, p1h, p1l);

    // ---- depth step 1 (prev = mb1 planes, dense) ----
    k_resonance4<<<128, 256>>>(adj);
    k_gemm_f2<HH><<<dim3(5, AR / 128), 128>>>(p_msg, W_h1, p_maW, HH);
    k_bondstep_mma<0, 0, 1><<<dim3(5, BR / 128), 256, SMEM_MMA>>>(
        p1h, p1l, wt1h, wt1l, p_inbond, p_maW, adj, mb_final, nullptr, nullptr);

    // ---- readout ----
    k_output<<<dim3(5, 32), 256>>>(W_o, b_o, out);
}

// round 17
// speedup vs baseline: 1.1012x; 1.0253x over previous
#include <cuda_runtime.h>
#include <cuda_bf16.h>
#include <math.h>
#include <stdint.h>

// Problem constants
#define GG 32
#define NA 64
#define HH 300
#define AF 133
#define BF 147
#define AR (GG*NA)     // 2048
#define BR (GG*NA*NA)  // 131072
#define KP 320         // padded K for bond-step planes (cols [300,320) stay zero)
#define KPI 160        // padded K for input_bond GEMM (BF=147 -> 160)
#define NIT_KP 10      // KP/32 mainloop iterations; last iteration: ks=0 only (K<=304)

// Scratch (zero-initialized device globals; allocation-free)
__device__ float g_input_atom[AR*HH];
__device__ float g_msg_atom[AR*HH];
__device__ float g_agg[AR*HH];
__device__ float g_maW[AR*HH];
__device__ float g_input_bond[BR*HH];   // fp32 ib (zero rows stay zero-init)
__device__ float g_mbB[BR*HH];          // fallback mb_final
__device__ float g_Cc[(size_t)BR*HH];   // compacted C = prev@W (step 0)
__device__ float g_sm[BR];
__device__ int   g_cnt;
__device__ int   g_rows[BR];
__device__ int   g_slot[BR];
// bf16 hi/lo planes (pads + zero rows never written -> stay zero)
__device__ __nv_bfloat16 g_P0h[(size_t)BR*KP];
__device__ __nv_bfloat16 g_P0l[(size_t)BR*KP];
__device__ __nv_bfloat16 g_P1h[(size_t)BR*KP];
__device__ __nv_bfloat16 g_P1l[(size_t)BR*KP];
__device__ __nv_bfloat16 g_Wt0h[KP*KP];
__device__ __nv_bfloat16 g_Wt0l[KP*KP];
__device__ __nv_bfloat16 g_Wt1h[KP*KP];
__device__ __nv_bfloat16 g_Wt1l[KP*KP];
__device__ __nv_bfloat16 g_WtIh[HH*KPI];
__device__ __nv_bfloat16 g_WtIl[HH*KPI];

// ---------------------------------------------------------------------------
// f32x2 helpers
// ---------------------------------------------------------------------------
__device__ __forceinline__ unsigned long long pack2(float x, float y) {
    unsigned long long r;
    asm("mov.b64 %0, {%1, %2};" : "=l"(r)
        : "r"(__float_as_uint(x)), "r"(__float_as_uint(y)));
    return r;
}
__device__ __forceinline__ void ffma2(unsigned long long& d, unsigned long long a,
                                      unsigned long long b) {
    asm("fma.rn.f32x2 %0, %1, %2, %3;" : "=l"(d) : "l"(a), "l"(b), "l"(d));
}
__device__ __forceinline__ float2 unpack2(unsigned long long v) {
    unsigned lo, hi;
    asm("mov.b64 {%0, %1}, %2;" : "=r"(lo), "=r"(hi) : "l"(v));
    return make_float2(__uint_as_float(lo), __uint_as_float(hi));
}

#define MMA_BF16(c, a, b0, b1) \
    asm volatile("mma.sync.aligned.m16n8k16.row.col.f32.bf16.bf16.f32 " \
                 "{%0,%1,%2,%3}, {%4,%5,%6,%7}, {%8,%9}, {%0,%1,%2,%3};" \
                 : "+f"((c)[0]), "+f"((c)[1]), "+f"((c)[2]), "+f"((c)[3]) \
                 : "r"((a)[0]), "r"((a)[1]), "r"((a)[2]), "r"((a)[3]), \
                   "r"(b0), "r"(b1))

#define LDSM_X4(R, A) \
    asm volatile("ldmatrix.sync.aligned.m8n8.x4.shared.b16 {%0,%1,%2,%3}, [%4];" \
                 : "=r"((R)[0]), "=r"((R)[1]), "=r"((R)[2]), "=r"((R)[3]) : "r"(A))

__device__ __forceinline__ uint32_t lds_addr(const void* p) {
    return (uint32_t)__cvta_generic_to_shared(p);
}

__device__ __forceinline__ void split_bf16(float v, __nv_bfloat16& h, __nv_bfloat16& l) {
    h = __float2bfloat16(v);
    l = __float2bfloat16(v - __bfloat162float(h));
}

// ---------------------------------------------------------------------------
// Sparse row compaction (adj is binary; ~30% density) + inverse slot map
// ---------------------------------------------------------------------------
__global__ void k_reset() { if (threadIdx.x == 0) g_cnt = 0; }

__global__ void k_compact(const float* __restrict__ adj) {
    int i = blockIdx.x * 256 + threadIdx.x;
    if (i < BR) {
        if (adj[i] != 0.f) {
            int idx = atomicAdd(&g_cnt, 1);
            g_rows[idx] = i;
            g_slot[i] = idx;
        } else {
            g_slot[i] = -1;
        }
    }
}

// ---------------------------------------------------------------------------
// W transpose + split (bond-step weights, KP layout)
// ---------------------------------------------------------------------------
__global__ void k_convW(const float* __restrict__ W,
                        __nv_bfloat16* __restrict__ hi, __nv_bfloat16* __restrict__ lo) {
    int n = blockIdx.x;
    int k = threadIdx.x;
    if (k < HH) {
        float v = W[(size_t)k * HH + n];
        __nv_bfloat16 h, l;
        split_bf16(v, h, l);
        hi[(size_t)n * KP + k] = h;
        lo[(size_t)n * KP + k] = l;
    }
}

// W_i_bond transpose + split (KPI layout, k in [BF,KPI) stays zero-init)
__global__ void k_convWi(const float* __restrict__ W,
                         __nv_bfloat16* __restrict__ hi, __nv_bfloat16* __restrict__ lo) {
    int n = blockIdx.x;          // 0..299
    int k = threadIdx.x;         // 0..159
    if (k < BF) {
        float v = W[(size_t)k * HH + n];
        __nv_bfloat16 h, l;
        split_bf16(v, h, l);
        hi[(size_t)n * KPI + k] = h;
        lo[(size_t)n * KPI + k] = l;
    }
}

// ---------------------------------------------------------------------------
// input_bond via mma.sync: compacted rows only.
// ---------------------------------------------------------------------------
__global__ __launch_bounds__(256)
void k_inbond_mma(const float* __restrict__ A,
                  const __nv_bfloat16* __restrict__ pWh, const __nv_bfloat16* __restrict__ pWl,
                  float* __restrict__ Co,
                  __nv_bfloat16* __restrict__ pH, __nv_bfloat16* __restrict__ pL) {
    extern __shared__ __align__(16) char smraw[];
    __nv_bfloat16 (*sAh)[40] = (__nv_bfloat16(*)[40])(smraw + 0);
    __nv_bfloat16 (*sAl)[40] = (__nv_bfloat16(*)[40])(smraw + 10240);
    __nv_bfloat16 (*sBh)[40] = (__nv_bfloat16(*)[40])(smraw + 20480);
    __nv_bfloat16 (*sBl)[40] = (__nv_bfloat16(*)[40])(smraw + 25600);

    const int cnt = g_cnt;
    const int row0 = blockIdx.y * 128;
    if (row0 >= cnt) return;
    const int col0 = blockIdx.x * 64;
    const int tid = threadIdx.x;
    const int w   = tid >> 5;
    const int rw  = w & 3;
    const int cw  = w >> 2;
    const int lane = tid & 31;
    const int gid = lane >> 2;
    const int q   = lane & 3;

    const int arow  = tid >> 1, ahalf = tid & 1;
    const int bn    = tid >> 2, bpart = tid & 3;
    const int grow  = (row0 + arow < cnt) ? g_rows[row0 + arow] : -1;

    const int aR = rw * 32 + (lane & 15);
    const int aC = (lane >> 4) * 8;
    const uint32_t addrAh = lds_addr(&sAh[aR][aC]);
    const uint32_t addrAl = lds_addr(&sAl[aR][aC]);
    const int bR = cw * 32 + ((lane >> 4) & 1) * 8 + (lane & 7);
    const int bC = ((lane >> 3) & 1) * 8;
    const uint32_t addrBh = lds_addr(&sBh[bR][bC]);
    const uint32_t addrBl = lds_addr(&sBl[bR][bC]);

    float acc[2][4][4];
    #pragma unroll
    for (int mt = 0; mt < 2; mt++)
        #pragma unroll
        for (int nt = 0; nt < 4; nt++)
            #pragma unroll
            for (int e = 0; e < 4; e++) acc[mt][nt][e] = 0.f;

    int k0 = 0;
    for (int it = 0; it < KPI / 32; ++it) {
        __syncthreads();
        {
            int kb = ahalf * 16;
            #pragma unroll
            for (int e = 0; e < 16; e++) {
                int k = k0 + kb + e;
                float v = (grow >= 0 && k < BF) ? A[(size_t)grow * BF + k] : 0.f;
                __nv_bfloat16 vh, vl;
                split_bf16(v, vh, vl);
                sAh[arow][kb + e] = vh;
                sAl[arow][kb + e] = vl;
            }
        }
        {
            const __nv_bfloat16* bBh = pWh + (size_t)(col0 + bn) * KPI + k0 + bpart * 8;
            const __nv_bfloat16* bBl = pWl + (size_t)(col0 + bn) * KPI + k0 + bpart * 8;
            *(uint4*)&sBh[bn][bpart * 8] = *(const uint4*)bBh;
            *(uint4*)&sBl[bn][bpart * 8] = *(const uint4*)bBl;
        }
        __syncthreads();
        #pragma unroll
        for (int ks = 0; ks < 2; ++ks) {
            const uint32_t ko = ks * 32;
            uint32_t afh[2][4], afl[2][4], bfh[2][4], bfl[2][4];
            #pragma unroll
            for (int mt = 0; mt < 2; mt++) {
                LDSM_X4(afh[mt], addrAh + mt * 1280 + ko);
                LDSM_X4(afl[mt], addrAl + mt * 1280 + ko);
            }
            #pragma unroll
            for (int p = 0; p < 2; p++) {
                LDSM_X4(bfh[p], addrBh + p * 1280 + ko);
                LDSM_X4(bfl[p], addrBl + p * 1280 + ko);
            }
            #pragma unroll
            for (int p = 0; p < 2; p++)
                #pragma unroll
                for (int s = 0; s < 2; s++) {
                    const int nt = 2 * p + s;
                    #pragma unroll
                    for (int mt = 0; mt < 2; mt++) {
                        MMA_BF16(acc[mt][nt], afh[mt], bfh[p][2 * s], bfh[p][2 * s + 1]);
                        MMA_BF16(acc[mt][nt], afh[mt], bfl[p][2 * s], bfl[p][2 * s + 1]);
                        MMA_BF16(acc[mt][nt], afl[mt], bfh[p][2 * s], bfh[p][2 * s + 1]);
                    }
                }
        }
        k0 += 32;
    }

    #pragma unroll
    for (int mt = 0; mt < 2; mt++) {
        #pragma unroll
        for (int rp = 0; rp < 2; rp++) {
            int lr = rw * 32 + mt * 16 + gid + rp * 8;
            int slot = row0 + lr;
            if (slot < cnt) {
                size_t row = g_rows[slot];
                #pragma unroll
                for (int nt = 0; nt < 4; nt++) {
                    int c = cw * 32 + nt * 8 + q * 2;
                    int h = col0 + c;
                    if (h < HH) {
                        float v0 = fmaxf(acc[mt][nt][rp * 2 + 0], 0.f);
                        float v1 = fmaxf(acc[mt][nt][rp * 2 + 1], 0.f);
                        *(float2*)&Co[row * HH + h] = make_float2(v0, v1);
                        __nv_bfloat16 h0, l0, h1, l1;
                        split_bf16(v0, h0, l0);
                        split_bf16(v1, h1, l1);
                        __nv_bfloat162 hp; hp.x = h0; hp.y = h1;
                        __nv_bfloat162 lp; lp.x = l0; lp.y = l1;
                        *(__nv_bfloat162*)&pH[row * KP + h] = hp;
                        *(__nv_bfloat162*)&pL[row * KP + h] = lp;
                    }
                }
            }
        }
    }
}

// ---------------------------------------------------------------------------
// f32x2 SGEMM (maW only): C = A @ W
// ---------------------------------------------------------------------------
#define BKg 12
template<int K>
__global__ __launch_bounds__(128, 3)
void k_gemm_f2(const float* __restrict__ A, const float* __restrict__ W,
               float* __restrict__ Co, int N) {
    const int row0 = blockIdx.y * 128;
    const int col0 = blockIdx.x * 64;
    __shared__ __align__(16) float As[BKg][132];
    __shared__ __align__(16) float Bs[BKg][72];
    const int tid = threadIdx.x;
    const int rg = tid >> 3;
    const int cg = tid & 7;

    int ar[3], ac4[3];
    #pragma unroll
    for (int q = 0; q < 3; q++) {
        int l = q * 128 + tid;
        ar[q]  = l / 3;
        ac4[q] = l - ar[q] * 3;
    }
    const int bk0  = tid >> 4;
    const int bk1  = (tid + 128) >> 4;
    const int bc4  = tid & 15;
    const bool hasB1  = (tid < 64);
    const bool bcolOK = (col0 + 4 * bc4 + 4 <= N);

    unsigned long long acc[8][4];
    #pragma unroll
    for (int i = 0; i < 8; i++)
        #pragma unroll
        for (int p = 0; p < 4; p++) acc[i][p] = 0ull;

    float4 ra[3], rb0, rb1;
    auto load_tile = [&](int k0) {
        #pragma unroll
        for (int q = 0; q < 3; q++)
            ra[q] = *(const float4*)&A[(size_t)(row0 + ar[q]) * K + k0 + 4 * ac4[q]];
        {
            int gk = k0 + bk0;
            rb0 = (gk < K && bcolOK) ? *(const float4*)&W[(size_t)gk * N + col0 + 4 * bc4]
                                     : make_float4(0.f, 0.f, 0.f, 0.f);
        }
        if (hasB1) {
            int gk = k0 + bk1;
            rb1 = (gk < K && bcolOK) ? *(const float4*)&W[(size_t)gk * N + col0 + 4 * bc4]
                                     : make_float4(0.f, 0.f, 0.f, 0.f);
        }
    };

    const int nIter = (K + BKg - 1) / BKg;
    load_tile(0);
    int k0 = 0;
    for (int it = 0; it < nIter; ++it) {
        __syncthreads();
        #pragma unroll
        for (int q = 0; q < 3; q++) {
            int kb = 4 * ac4[q];
            As[kb + 0][ar[q]] = ra[q].x;
            As[kb + 1][ar[q]] = ra[q].y;
            As[kb + 2][ar[q]] = ra[q].z;
            As[kb + 3][ar[q]] = ra[q].w;
        }
        *(float4*)&Bs[bk0][4 * bc4] = rb0;
        if (hasB1) *(float4*)&Bs[bk1][4 * bc4] = rb1;
        __syncthreads();
        if (it + 1 < nIter) load_tile(k0 + BKg);
        #pragma unroll
        for (int kk = 0; kk < BKg; ++kk) {
            float4 a0 = *(const float4*)&As[kk][rg * 8];
            float4 a1 = *(const float4*)&As[kk][rg * 8 + 4];
            ulonglong2 b01 = *(const ulonglong2*)&Bs[kk][cg * 8];
            ulonglong2 b23 = *(const ulonglong2*)&Bs[kk][cg * 8 + 4];
            float av[8] = {a0.x, a0.y, a0.z, a0.w, a1.x, a1.y, a1.z, a1.w};
            #pragma unroll
            for (int i = 0; i < 8; i++) {
                unsigned long long ap = pack2(av[i], av[i]);
                ffma2(acc[i][0], ap, b01.x);
                ffma2(acc[i][1], ap, b01.y);
                ffma2(acc[i][2], ap, b23.x);
                ffma2(acc[i][3], ap, b23.y);
            }
        }
        k0 += BKg;
    }

    const bool fastcol = (col0 + 64 <= N);
    #pragma unroll
    for (int i = 0; i < 8; i++) {
        size_t row = row0 + rg * 8 + i;
        float v[8];
        #pragma unroll
        for (int p = 0; p < 4; p++) {
            float2 f = unpack2(acc[i][p]);
            v[2 * p] = f.x; v[2 * p + 1] = f.y;
        }
        size_t base = row * N + col0 + cg * 8;
        if (fastcol) {
            *(float4*)&Co[base]     = make_float4(v[0], v[1], v[2], v[3]);
            *(float4*)&Co[base + 4] = make_float4(v[4], v[5], v[6], v[7]);
        } else {
            #pragma unroll
            for (int jj = 0; jj < 8; jj++)
                if (col0 + cg * 8 + jj < N) Co[base + jj] = v[jj];
        }
    }
}

// ---------------------------------------------------------------------------
// Compacted-row mma.sync GEMM (step 0): Cc[slot,:] = prev@W
// ---------------------------------------------------------------------------
__global__ __launch_bounds__(256)
void k_gemmc_mma(const __nv_bfloat16* __restrict__ pAh, const __nv_bfloat16* __restrict__ pAl,
                 const __nv_bfloat16* __restrict__ pWh, const __nv_bfloat16* __restrict__ pWl,
                 float* __restrict__ Cc) {
    extern __shared__ __align__(16) char smraw[];
    __nv_bfloat16 (*sAh)[40] = (__nv_bfloat16(*)[40])(smraw + 0);
    __nv_bfloat16 (*sAl)[40] = (__nv_bfloat16(*)[40])(smraw + 10240);
    __nv_bfloat16 (*sBh)[40] = (__nv_bfloat16(*)[40])(smraw + 20480);
    __nv_bfloat16 (*sBl)[40] = (__nv_bfloat16(*)[40])(smraw + 25600);

    const int cnt = g_cnt;
    const int row0 = blockIdx.y * 128;
    if (row0 >= cnt) return;
    const int col0 = blockIdx.x * 64;
    const int tid = threadIdx.x;
    const int w   = tid >> 5;
    const int rw  = w & 3;
    const int cw  = w >> 2;
    const int lane = tid & 31;
    const int gid = lane >> 2;
    const int q   = lane & 3;

    const int arow  = tid >> 1, apart = tid & 1;
    const int bn    = tid >> 2, bpart = tid & 3;
    const int grow  = (row0 + arow < cnt) ? g_rows[row0 + arow] : -1;

    const int aR = rw * 32 + (lane & 15);
    const int aC = (lane >> 4) * 8;
    const uint32_t addrAh = lds_addr(&sAh[aR][aC]);
    const uint32_t addrAl = lds_addr(&sAl[aR][aC]);
    const int bR = cw * 32 + ((lane >> 4) & 1) * 8 + (lane & 7);
    const int bC = ((lane >> 3) & 1) * 8;
    const uint32_t addrBh = lds_addr(&sBh[bR][bC]);
    const uint32_t addrBl = lds_addr(&sBl[bR][bC]);

    float acc[2][4][4];
    #pragma unroll
    for (int mt = 0; mt < 2; mt++)
        #pragma unroll
        for (int nt = 0; nt < 4; nt++)
            #pragma unroll
            for (int e = 0; e < 4; e++) acc[mt][nt][e] = 0.f;

    uint4 rAh[2], rAl[2], rBh, rBl;
    auto load_tile = [&](int k0) {
        if (grow >= 0) {
            const __nv_bfloat16* bAh = pAh + (size_t)grow * KP + k0 + apart * 16;
            const __nv_bfloat16* bAl = pAl + (size_t)grow * KP + k0 + apart * 16;
            rAh[0] = *(const uint4*)bAh;  rAh[1] = *(const uint4*)(bAh + 8);
            rAl[0] = *(const uint4*)bAl;  rAl[1] = *(const uint4*)(bAl + 8);
        } else {
            rAh[0] = rAh[1] = rAl[0] = rAl[1] = make_uint4(0, 0, 0, 0);
        }
        const __nv_bfloat16* bBh = pWh + (size_t)(col0 + bn) * KP + k0 + bpart * 8;
        const __nv_bfloat16* bBl = pWl + (size_t)(col0 + bn) * KP + k0 + bpart * 8;
        rBh = *(const uint4*)bBh;
        rBl = *(const uint4*)bBl;
    };

    load_tile(0);
    int k0 = 0;
    for (int it = 0; it < NIT_KP; ++it) {
        __syncthreads();
        *(uint4*)&sAh[arow][apart * 16]     = rAh[0];
        *(uint4*)&sAh[arow][apart * 16 + 8] = rAh[1];
        *(uint4*)&sAl[arow][apart * 16]     = rAl[0];
        *(uint4*)&sAl[arow][apart * 16 + 8] = rAl[1];
        *(uint4*)&sBh[bn][bpart * 8] = rBh;
        *(uint4*)&sBl[bn][bpart * 8] = rBl;
        __syncthreads();
        if (it + 1 < NIT_KP) load_tile(k0 + 32);
        const int nks = (it == NIT_KP - 1) ? 1 : 2;   // tail: cols 304-319 are zero
        for (int ks = 0; ks < nks; ++ks) {
            const uint32_t ko = ks * 32;
            uint32_t afh[2][4], afl[2][4], bfh[2][4], bfl[2][4];
            #pragma unroll
            for (int mt = 0; mt < 2; mt++) {
                LDSM_X4(afh[mt], addrAh + mt * 1280 + ko);
                LDSM_X4(afl[mt], addrAl + mt * 1280 + ko);
            }
            #pragma unroll
            for (int p = 0; p < 2; p++) {
                LDSM_X4(bfh[p], addrBh + p * 1280 + ko);
                LDSM_X4(bfl[p], addrBl + p * 1280 + ko);
            }
            #pragma unroll
            for (int p = 0; p < 2; p++)
                #pragma unroll
                for (int s = 0; s < 2; s++) {
                    const int nt = 2 * p + s;
                    #pragma unroll
                    for (int mt = 0; mt < 2; mt++) {
                        MMA_BF16(acc[mt][nt], afh[mt], bfh[p][2 * s], bfh[p][2 * s + 1]);
                        MMA_BF16(acc[mt][nt], afh[mt], bfl[p][2 * s], bfl[p][2 * s + 1]);
                        MMA_BF16(acc[mt][nt], afl[mt], bfh[p][2 * s], bfh[p][2 * s + 1]);
                    }
                }
        }
        k0 += 32;
    }

    #pragma unroll
    for (int mt = 0; mt < 2; mt++) {
        #pragma unroll
        for (int rp = 0; rp < 2; rp++) {
            int lr = rw * 32 + mt * 16 + gid + rp * 8;
            int slot = row0 + lr;
            if (slot < cnt) {
                #pragma unroll
                for (int nt = 0; nt < 4; nt++) {
                    int c = cw * 32 + nt * 8 + q * 2;
                    int h = col0 + c;
                    if (h < HH) {
                        *(float2*)&Cc[(size_t)slot * HH + h] =
                            make_float2(acc[mt][nt][rp * 2 + 0], acc[mt][nt][rp * 2 + 1]);
                    }
                }
            }
        }
    }
}

// ---------------------------------------------------------------------------
// Step-0 epilogue, 160 threads, one float2 column per thread.
// Round-17: skip ib loads for rows with adj[g,i,j]==0 (ib row is exactly 0).
// ---------------------------------------------------------------------------
__global__ void k_epilogue0(const float* __restrict__ ib, const float* __restrict__ maW,
                            const float* __restrict__ Cc, const float* __restrict__ adj,
                            __nv_bfloat16* __restrict__ pOh, __nv_bfloat16* __restrict__ pOl) {
    int gj = blockIdx.x;
    int g = gj >> 6, j = gj & 63;
    __shared__ float adjT[64], smv[64], adjI[64];
    __shared__ int   slots[64];
    int tid = threadIdx.x;        // 160
    if (tid < 64) {
        adjT[tid]  = adj[((size_t)(g * 64 + j)) * 64 + tid];     // adj[g,j,i]
        smv[tid]   = g_sm[((size_t)(g * 64 + tid)) * 64 + j];
        slots[tid] = g_slot[((size_t)(g * 64 + j)) * 64 + tid];
        adjI[tid]  = adj[((size_t)(g * 64 + tid)) * 64 + j];     // adj[g,i,j] (ib guard)
    }
    __syncthreads();
    const int h0 = 2 * tid;
    if (h0 >= HH) return;
    float2 s0 = make_float2(0.f, 0.f);
    float2 m0 = make_float2(-INFINITY, -INFINITY);
    for (int i = 0; i < 64; ++i) {
        size_t rowOut = ((size_t)(g * 64 + i) * 64 + j);
        size_t obase  = rowOut * HH;
        size_t pbase  = rowOut * KP;
        size_t rowM   = (size_t)(g * 64 + i) * HH;
        int slot = slots[i];
        float a = adjT[i], wv = smv[i];
        float2 ibv = (adjI[i] != 0.f) ? *(const float2*)&ib[obase + h0]
                                      : make_float2(0.f, 0.f);
        float2 mw  = *(const float2*)&maW[rowM + h0];
        float2 cv  = (slot >= 0) ? *(const float2*)&Cc[(size_t)slot * HH + h0]
                                 : make_float2(0.f, 0.f);
        float v0 = fmaxf(ibv.x + a * mw.x - cv.x, 0.f) * wv;
        float v1 = fmaxf(ibv.y + a * mw.y - cv.y, 0.f) * wv;
        __nv_bfloat16 vh0, vl0, vh1, vl1;
        split_bf16(v0, vh0, vl0);
        split_bf16(v1, vh1, vl1);
        __nv_bfloat162 hp; hp.x = vh0; hp.y = vh1;
        __nv_bfloat162 lp; lp.x = vl0; lp.y = vl1;
        *(__nv_bfloat162*)&pOh[pbase + h0] = hp;
        *(__nv_bfloat162*)&pOl[pbase + h0] = lp;
        s0.x += v0;  s0.y += v1;
        m0.x = fmaxf(m0.x, v0);  m0.y = fmaxf(m0.y, v1);
    }
    {
        size_t base = (size_t)(g * 64 + j) * HH;
        float2 cur = *(float2*)&g_msg_atom[base + h0];
        cur.x += s0.x * (1.f / (1.f + expf(-m0.x)));
        cur.y += s0.y * (1.f / (1.f + expf(-m0.y)));
        *(float2*)&g_msg_atom[base + h0] = cur;
    }
}

// ---------------------------------------------------------------------------
// Tensor-core fused bond step (step 1). Round-17: adjacency-guarded ib loads.
// smem: adjI2 at 65792 (2x64 floats), total 66304 <= 66560.
// ---------------------------------------------------------------------------
template<int UPDATE, int EMIT, int STORE>
__global__ __launch_bounds__(256)
void k_bondstep_mma(const __nv_bfloat16* __restrict__ pAh, const __nv_bfloat16* __restrict__ pAl,
                    const __nv_bfloat16* __restrict__ pWh, const __nv_bfloat16* __restrict__ pWl,
                    const float* __restrict__ ib, const float* __restrict__ maW,
                    const float* __restrict__ adj, float* __restrict__ mbout,
                    __nv_bfloat16* __restrict__ pOh, __nv_bfloat16* __restrict__ pOl) {
    extern __shared__ __align__(16) char smraw[];
    __nv_bfloat16 (*sAh)[40] = (__nv_bfloat16(*)[40])(smraw + 0);
    __nv_bfloat16 (*sAl)[40] = (__nv_bfloat16(*)[40])(smraw + 10240);
    __nv_bfloat16 (*sBh)[40] = (__nv_bfloat16(*)[40])(smraw + 20480);
    __nv_bfloat16 (*sBl)[40] = (__nv_bfloat16(*)[40])(smraw + 25600);
    float (*maWs)[68]        = (float(*)[68])(smraw + 30720);
    float (*psum)[65]        = (float(*)[65])(smraw + 48128);
    float (*pmax)[65]        = (float(*)[65])(smraw + 56448);
    float (*adjs)[64]        = (float(*)[64])(smraw + 64768);
    float (*smvv)[64]        = (float(*)[64])(smraw + 65280);
    float (*adjI2)[64]       = (float(*)[64])(smraw + 65792);   // adj[g,y,x0+xl]

    const int row0 = blockIdx.y * 128;
    const int col0 = blockIdx.x * 64;
    const int g  = row0 >> 12;
    const int x0 = (row0 >> 6) & 63;
    const int tid = threadIdx.x;
    const int w   = tid >> 5;
    const int rw  = w & 3;
    const int cw  = w >> 2;
    const int lane = tid & 31;
    const int gid = lane >> 2;
    const int q   = lane & 3;

    if (tid < 128) {
        int xl = tid >> 6, y = tid & 63;
        adjs[xl][y]  = adj[(size_t)(g * 64 + x0 + xl) * 64 + y];
        smvv[xl][y]  = g_sm[(size_t)(g * 64 + y) * 64 + x0 + xl];
        adjI2[xl][y] = adj[(size_t)(g * 64 + y) * 64 + x0 + xl];   // ib guard
    }
    for (int l = tid; l < 64 * 16; l += 256) {
        int y = l >> 4, c4 = (l & 15) * 4;
        int c = col0 + c4;
        float4 v;
        if (c + 4 <= HH) v = *(const float4*)&maW[(size_t)(g * 64 + y) * HH + c];
        else {
            float t[4];
            #pragma unroll
            for (int e = 0; e < 4; e++)
                t[e] = (c + e < HH) ? maW[(size_t)(g * 64 + y) * HH + c + e] : 0.f;
            v = make_float4(t[0], t[1], t[2], t[3]);
        }
        *(float4*)&maWs[y][c4] = v;
    }

    const int arow  = tid >> 1, apart = tid & 1;
    const int bn    = tid >> 2, bpart = tid & 3;

    const int aR = rw * 32 + (lane & 15);
    const int aC = (lane >> 4) * 8;
    const uint32_t addrAh = lds_addr(&sAh[aR][aC]);
    const uint32_t addrAl = lds_addr(&sAl[aR][aC]);
    const int bR = cw * 32 + ((lane >> 4) & 1) * 8 + (lane & 7);
    const int bC = ((lane >> 3) & 1) * 8;
    const uint32_t addrBh = lds_addr(&sBh[bR][bC]);
    const uint32_t addrBl = lds_addr(&sBl[bR][bC]);

    float acc[2][4][4];
    #pragma unroll
    for (int mt = 0; mt < 2; mt++)
        #pragma unroll
        for (int nt = 0; nt < 4; nt++)
            #pragma unroll
            for (int e = 0; e < 4; e++) acc[mt][nt][e] = 0.f;

    uint4 rAh[2], rAl[2], rBh, rBl;
    auto load_tile = [&](int k0) {
        const __nv_bfloat16* bAh = pAh + (size_t)(row0 + arow) * KP + k0 + apart * 16;
        const __nv_bfloat16* bAl = pAl + (size_t)(row0 + arow) * KP + k0 + apart * 16;
        rAh[0] = *(const uint4*)bAh;  rAh[1] = *(const uint4*)(bAh + 8);
        rAl[0] = *(const uint4*)bAl;  rAl[1] = *(const uint4*)(bAl + 8);
        const __nv_bfloat16* bBh = pWh + (size_t)(col0 + bn) * KP + k0 + bpart * 8;
        const __nv_bfloat16* bBl = pWl + (size_t)(col0 + bn) * KP + k0 + bpart * 8;
        rBh = *(const uint4*)bBh;
        rBl = *(const uint4*)bBl;
    };

    load_tile(0);
    int k0 = 0;
    for (int it = 0; it < NIT_KP; ++it) {
        __syncthreads();
        *(uint4*)&sAh[arow][apart * 16]     = rAh[0];
        *(uint4*)&sAh[arow][apart * 16 + 8] = rAh[1];
        *(uint4*)&sAl[arow][apart * 16]     = rAl[0];
        *(uint4*)&sAl[arow][apart * 16 + 8] = rAl[1];
        *(uint4*)&sBh[bn][bpart * 8] = rBh;
        *(uint4*)&sBl[bn][bpart * 8] = rBl;
        __syncthreads();
        if (it + 1 < NIT_KP) load_tile(k0 + 32);
        const int nks = (it == NIT_KP - 1) ? 1 : 2;   // tail: cols 304-319 are zero
        for (int ks = 0; ks < nks; ++ks) {
            const uint32_t ko = ks * 32;
            uint32_t afh[2][4], afl[2][4], bfh[2][4], bfl[2][4];
            #pragma unroll
            for (int mt = 0; mt < 2; mt++) {
                LDSM_X4(afh[mt], addrAh + mt * 1280 + ko);
                LDSM_X4(afl[mt], addrAl + mt * 1280 + ko);
            }
            #pragma unroll
            for (int p = 0; p < 2; p++) {
                LDSM_X4(bfh[p], addrBh + p * 1280 + ko);
                LDSM_X4(bfl[p], addrBl + p * 1280 + ko);
            }
            #pragma unroll
            for (int p = 0; p < 2; p++)
                #pragma unroll
                for (int s = 0; s < 2; s++) {
                    const int nt = 2 * p + s;
                    #pragma unroll
                    for (int mt = 0; mt < 2; mt++) {
                        MMA_BF16(acc[mt][nt], afh[mt], bfh[p][2 * s], bfh[p][2 * s + 1]);
                        MMA_BF16(acc[mt][nt], afh[mt], bfl[p][2 * s], bfl[p][2 * s + 1]);
                        MMA_BF16(acc[mt][nt], afl[mt], bfh[p][2 * s], bfh[p][2 * s + 1]);
                    }
                }
        }
        k0 += 32;
    }

    float tsum[4][2], tmax[4][2];
    #pragma unroll
    for (int nt = 0; nt < 4; nt++)
        #pragma unroll
        for (int p = 0; p < 2; p++) { tsum[nt][p] = 0.f; tmax[nt][p] = -INFINITY; }

    #pragma unroll
    for (int mt = 0; mt < 2; mt++) {
        #pragma unroll
        for (int rp = 0; rp < 2; rp++) {
            int lr = rw * 32 + mt * 16 + gid + rp * 8;
            int xl = lr >> 6, y = lr & 63;
            int x  = x0 + xl;
            float a = adjs[xl][y];
            float wv = smvv[xl][y];
            const bool hasIb = (adjI2[xl][y] != 0.f);
            size_t brow = (size_t)(g * 64 + y) * 64 + x;
            #pragma unroll
            for (int nt = 0; nt < 4; nt++) {
                int c = cw * 32 + nt * 8 + q * 2;
                int h = col0 + c;
                if (h < HH) {
                    size_t ob = brow * HH + h;
                    float2 ibv = hasIb ? *(const float2*)&ib[ob]
                                       : make_float2(0.f, 0.f);
                    float v0 = fmaxf(ibv.x + a * maWs[y][c]     - acc[mt][nt][rp * 2 + 0], 0.f) * wv;
                    float v1 = fmaxf(ibv.y + a * maWs[y][c + 1] - acc[mt][nt][rp * 2 + 1], 0.f) * wv;
                    if (STORE) *(float2*)&mbout[ob] = make_float2(v0, v1);
                    if (EMIT) {
                        __nv_bfloat16 h0, l0, h1, l1;
                        split_bf16(v0, h0, l0);
                        split_bf16(v1, h1, l1);
                        size_t pb = brow * KP + h;
                        __nv_bfloat162 hp; hp.x = h0; hp.y = h1;
                        __nv_bfloat162 lp; lp.x = l0; lp.y = l1;
                        *(__nv_bfloat162*)&pOh[pb] = hp;
                        *(__nv_bfloat162*)&pOl[pb] = lp;
                    }
                    tsum[nt][0] += v0;  tmax[nt][0] = fmaxf(tmax[nt][0], v0);
                    tsum[nt][1] += v1;  tmax[nt][1] = fmaxf(tmax[nt][1], v1);
                }
            }
        }
    }
    {
        int slot = rw * 8 + gid;
        #pragma unroll
        for (int nt = 0; nt < 4; nt++) {
            int c = cw * 32 + nt * 8 + q * 2;
            psum[slot][c]     = tsum[nt][0];
            psum[slot][c + 1] = tsum[nt][1];
            pmax[slot][c]     = tmax[nt][0];
            pmax[slot][c + 1] = tmax[nt][1];
        }
    }
    __syncthreads();
    if (tid < 128) {
        int xl = tid >> 6, c = tid & 63;
        if (col0 + c < HH) {
            float s = 0.f, m = -INFINITY;
            #pragma unroll
            for (int r = 0; r < 16; r++) {
                s += psum[xl * 16 + r][c];
                m = fmaxf(m, pmax[xl * 16 + r][c]);
            }
            float aggv = s * (1.f / (1.f + expf(-m)));
            size_t idx = (size_t)(g * 64 + x0 + xl) * HH + col0 + c;
            if (UPDATE) g_msg_atom[idx] += aggv;
            else        g_agg[idx] = aggv;
        }
    }
}

// ---------------------------------------------------------------------------
// input_atom = relu(f_atoms @ W_i_atom) (also -> msg_atom)
// ---------------------------------------------------------------------------
__global__ void k_input_atom(const float* __restrict__ A, const float* __restrict__ W) {
    const int row0 = blockIdx.y * 64;
    const int col0 = blockIdx.x * 64;
    __shared__ float As[16][68];
    __shared__ float Bs[16][68];
    const int tid = threadIdx.x;
    const int tx = tid & 15, ty = tid >> 4;
    float acc[4][4] = {};
    for (int k0 = 0; k0 < AF; k0 += 16) {
        __syncthreads();
        {
            int kk = tid & 15;
            int k  = k0 + kk;
            #pragma unroll
            for (int qq = 0; qq < 4; qq++) {
                int r = (tid >> 4) + qq * 16;
                As[kk][r] = (k < AF) ? A[(row0 + r) * AF + k] : 0.f;
            }
        }
        {
            int nn = tid & 63;
            int c  = col0 + nn;
            #pragma unroll
            for (int qq = 0; qq < 4; qq++) {
                int kk = (tid >> 6) + qq * 4;
                int k  = k0 + kk;
                Bs[kk][nn] = (k < AF && c < HH) ? W[k * HH + c] : 0.f;
            }
        }
        __syncthreads();
        #pragma unroll
        for (int kk = 0; kk < 16; kk++) {
            float4 a4 = *(const float4*)&As[kk][ty * 4];
            float4 b4 = *(const float4*)&Bs[kk][tx * 4];
            float a[4] = {a4.x, a4.y, a4.z, a4.w};
            float b[4] = {b4.x, b4.y, b4.z, b4.w};
            #pragma unroll
            for (int i = 0; i < 4; i++)
                #pragma unroll
                for (int j = 0; j < 4; j++)
                    acc[i][j] += a[i] * b[j];
        }
    }
    #pragma unroll
    for (int i = 0; i < 4; i++) {
        int r = row0 + ty * 4 + i;
        #pragma unroll
        for (int j = 0; j < 4; j++) {
            int c = col0 + tx * 4 + j;
            if (c < HH) {
                float v = acc[i][j];
                v = v > 0.f ? v : 0.f;
                g_input_atom[r * HH + c] = v;
                g_msg_atom[r * HH + c]   = v;
            }
        }
    }
}

// ---------------------------------------------------------------------------
// agg over input_bond with adjacency skip — float2-vectorized.
// ---------------------------------------------------------------------------
__global__ void k_agg(const float* __restrict__ mb, const float* __restrict__ adj) {
    int gm = blockIdx.x;
    int g = gm >> 6, m = gm & 63;
    __shared__ float adjc[64];
    int tid = threadIdx.x;       // 160
    if (tid < 64) adjc[tid] = adj[(size_t)(g * 64 + tid) * 64 + m];
    __syncthreads();
    int h = 2 * tid;
    if (h >= HH) return;
    const float* base = mb + ((size_t)(g * 64) * 64 + m) * HH + h;
    float2 s = make_float2(0.f, 0.f);
    float2 mx = make_float2(0.f, 0.f);
    for (int n = 0; n < 64; n++) {
        if (adjc[n] != 0.f) {
            float2 v = *(const float2*)&base[(size_t)n * 64 * HH];
            s.x += v.x;  s.y += v.y;
            mx.x = fmaxf(mx.x, v.x);  mx.y = fmaxf(mx.y, v.y);
        }
    }
    size_t idx = (size_t)gm * HH + h;
    float2 cur = *(float2*)&g_msg_atom[idx];
    cur.x += s.x * (1.f / (1.f + expf(-mx.x)));
    cur.y += s.y * (1.f / (1.f + expf(-mx.y)));
    *(float2*)&g_msg_atom[idx] = cur;
}

// ---------------------------------------------------------------------------
// Resonance + softmax, 4 column-tiles per graph (128 blocks).
// ---------------------------------------------------------------------------
__global__ void k_resonance4(const float* __restrict__ adj) {
    int g  = blockIdx.x >> 2;
    int qt = blockIdx.x & 3;
    __shared__ float mt[64][101];
    __shared__ float rr[64][17];
    int tid = threadIdx.x;
    int tx = tid & 15;
    int ty = tid >> 4;
    float acc[4] = {};
    for (int c = 0; c < 3; ++c) {
        __syncthreads();
        for (int l = tid; l < 6400; l += 256) {
            int r = l / 100, k = l - r * 100;
            mt[r][k] = g_msg_atom[((size_t)(g * 64 + r)) * 300 + c * 100 + k];
        }
        __syncthreads();
        for (int kk = 0; kk < 100; ++kk) {
            float b = mt[qt * 16 + tx][kk];
            #pragma unroll
            for (int i = 0; i < 4; i++)
                acc[i] += mt[ty * 4 + i][kk] * b;
        }
    }
    #pragma unroll
    for (int i = 0; i < 4; i++)
        rr[ty * 4 + i][tx] = acc[i];
    __syncthreads();
    if (tid < 16) {
        int m = qt * 16 + tid;
        float mxv = -INFINITY;
        for (int n = 0; n < 64; n++) {
            float v = rr[n][tid] * adj[((size_t)(g * 64 + n)) * 64 + m];
            rr[n][tid] = v;
            mxv = fmaxf(mxv, v);
        }
        float sum = 0.f;
        for (int n = 0; n < 64; n++) {
            float e = expf(rr[n][tid] - mxv);
            rr[n][tid] = e;
            sum += e;
        }
        float inv = 1.f / sum;
        for (int n = 0; n < 64; n++)
            g_sm[(size_t)(g * 64 + n) * 64 + m] = rr[n][tid] * inv;
    }
}

// ---------------------------------------------------------------------------
__global__ void k_output(const float* __restrict__ W, const float* __restrict__ bias,
                         float* __restrict__ out) {
    const int row0 = blockIdx.y * 64;
    const int col0 = blockIdx.x * 64;
    __shared__ float As[16][68];
    __shared__ float Bs[16][68];
    const int tid = threadIdx.x;
    const int tx = tid & 15, ty = tid >> 4;
    float acc[4][4] = {};
    for (int k0 = 0; k0 < 900; k0 += 16) {
        __syncthreads();
        {
            int kk = tid & 15;
            int k  = k0 + kk;
            #pragma unroll
            for (int qq = 0; qq < 4; qq++) {
                int r = (tid >> 4) + qq * 16;
                int row = row0 + r;
                float v = 0.f;
                if (k < 900) {
                    if (k < 300)       v = g_agg[row * HH + k];
                    else if (k < 600)  v = g_msg_atom[row * HH + (k - 300)];
                    else               v = g_input_atom[row * HH + (k - 600)];
                }
                As[kk][r] = v;
            }
        }
        {
            int nn = tid & 63;
            int c  = col0 + nn;
            #pragma unroll
            for (int qq = 0; qq < 4; qq++) {
                int kk = (tid >> 6) + qq * 4;
                int k  = k0 + kk;
                Bs[kk][nn] = (k < 900 && c < HH) ? W[k * HH + c] : 0.f;
            }
        }
        __syncthreads();
        #pragma unroll
        for (int kk = 0; kk < 16; kk++) {
            float4 a4 = *(const float4*)&As[kk][ty * 4];
            float4 b4 = *(const float4*)&Bs[kk][tx * 4];
            float a[4] = {a4.x, a4.y, a4.z, a4.w};
            float b[4] = {b4.x, b4.y, b4.z, b4.w};
            #pragma unroll
            for (int i = 0; i < 4; i++)
                #pragma unroll
                for (int j = 0; j < 4; j++)
                    acc[i][j] += a[i] * b[j];
        }
    }
    #pragma unroll
    for (int i = 0; i < 4; i++) {
        int r = row0 + ty * 4 + i;
        #pragma unroll
        for (int j = 0; j < 4; j++) {
            int c = col0 + tx * 4 + j;
            if (c < HH) {
                float v = acc[i][j] + bias[c];
                out[r * HH + c] = v > 0.f ? v : 0.f;
            }
        }
    }
}

// ---------------------------------------------------------------------------
extern "C" void kernel_launch(void* const* d_in, const int* in_sizes, int n_in,
                              void* d_out, int out_size) {
    const float* f_atoms  = (const float*)d_in[0];
    const float* f_bonds  = (const float*)d_in[1];
    const float* adj      = (const float*)d_in[2];
    const float* W_i_atom = (const float*)d_in[3];
    const float* W_i_bond = (const float*)d_in[4];
    const float* W_h0     = (const float*)d_in[5];
    const float* W_h1     = (const float*)d_in[6];
    const float* W_o      = (const float*)d_in[7];
    const float* b_o      = (const float*)d_in[8];
    float* out = (float*)d_out;

    float *p_inbond = 0, *p_mbB = 0, *p_msg = 0, *p_maW = 0, *p_Cc = 0;
    __nv_bfloat16 *p0h = 0, *p0l = 0, *p1h = 0, *p1l = 0;
    __nv_bfloat16 *wt0h = 0, *wt0l = 0, *wt1h = 0, *wt1l = 0, *wtih = 0, *wtil = 0;
    cudaGetSymbolAddress((void**)&p_inbond, g_input_bond);
    cudaGetSymbolAddress((void**)&p_mbB, g_mbB);
    cudaGetSymbolAddress((void**)&p_msg, g_msg_atom);
    cudaGetSymbolAddress((void**)&p_maW, g_maW);
    cudaGetSymbolAddress((void**)&p_Cc, g_Cc);
    cudaGetSymbolAddress((void**)&p0h, g_P0h);
    cudaGetSymbolAddress((void**)&p0l, g_P0l);
    cudaGetSymbolAddress((void**)&p1h, g_P1h);
    cudaGetSymbolAddress((void**)&p1l, g_P1l);
    cudaGetSymbolAddress((void**)&wt0h, g_Wt0h);
    cudaGetSymbolAddress((void**)&wt0l, g_Wt0l);
    cudaGetSymbolAddress((void**)&wt1h, g_Wt1h);
    cudaGetSymbolAddress((void**)&wt1l, g_Wt1l);
    cudaGetSymbolAddress((void**)&wtih, g_WtIh);
    cudaGetSymbolAddress((void**)&wtil, g_WtIl);

    float* mb_final = (out_size >= AR * HH + BR * HH) ? (out + AR * HH) : p_mbB;

    const int SMEM_MMA = 66560;
    const int SMEM_GC  = 30720;
    cudaFuncSetAttribute(k_bondstep_mma<0, 0, 1>,
                         cudaFuncAttributeMaxDynamicSharedMemorySize, SMEM_MMA);
    cudaFuncSetAttribute(k_gemmc_mma,
                         cudaFuncAttributeMaxDynamicSharedMemorySize, SMEM_GC);
    cudaFuncSetAttribute(k_inbond_mma,
                         cudaFuncAttributeMaxDynamicSharedMemorySize, SMEM_GC);

    // sparsity compaction (adj binary, ~30% dense) + slot map
    k_reset<<<1, 32>>>();
    k_compact<<<(BR + 255) / 256, 256>>>(adj);

    k_input_atom<<<dim3(5, 32), 256>>>(f_atoms, W_i_atom);
    k_convW<<<HH, KP>>>(W_h0, wt0h, wt0l);
    k_convW<<<HH, KP>>>(W_h1, wt1h, wt1l);
    k_convWi<<<HH, KPI>>>(W_i_bond, wtih, wtil);
    // input_bond over nonzero rows only via tensor cores (fp32 ib + P0 planes)
    k_inbond_mma<<<dim3(5, BR / 128), 256, SMEM_GC>>>(f_bonds, wtih, wtil,
                                                      p_inbond, p0h, p0l);

    // ---- depth step 0 (prev = input_bond, 70% zero rows -> compacted GEMM) ----
    k_agg<<<2048, 160>>>(p_inbond, adj);
    k_resonance4<<<128, 256>>>(adj);
    k_gemm_f2<HH><<<dim3(5, AR / 128), 128>>>(p_msg, W_h0, p_maW, HH);
    k_gemmc_mma<<<dim3(5, BR / 128), 256, SMEM_GC>>>(p0h, p0l, wt0h, wt0l, p_Cc);
    k_epilogue0<<<2048, 160>>>(p_inbond, p_maW, p_Cc, adj, p1h, p1l);

    // ---- depth step 1 (prev = mb1 planes, dense) ----
    k_resonance4<<<128, 256>>>(adj);
    k_gemm_f2<HH><<<dim3(5, AR / 128), 128>>>(p_msg, W_h1, p_maW, HH);
    k_bondstep_mma<0, 0, 1><<<dim3(5, BR / 128), 256, SMEM_MMA>>>(
        p1h, p1l, wt1h, wt1l, p_inbond, p_maW, adj, mb_final, nullptr, nullptr);

    // ---- readout ----
    k_output<<<dim3(5, 32), 256>>>(W_o, b_o, out);
}